// round 9
// baseline (speedup 1.0000x reference)
#include <cuda_runtime.h>
#include <cuda_fp16.h>
#include <stdint.h>
#include <math.h>

#define N_NODES 50000
#define N_EDGES 800000
#define D 128
#define H 256
#define NMAX 65536

// ---------------- device scratch ----------------
__device__ __align__(16) float  g_n  [(size_t)N_NODES * D];
__device__ __align__(16) __half g_nh [(size_t)N_NODES * D];
__device__ __align__(16) __half g_eh [(size_t)N_EDGES * D];
__device__ __align__(16) __half g_Psh[(size_t)N_NODES * H];
__device__ __align__(16) __half g_Prh[(size_t)N_NODES * H];
__device__ __align__(16) float  g_agg[(size_t)N_NODES * D];
// pre-transposed fp16 weights ([N][K] K-major)
__device__ __align__(16) __half g_wnt[128 * 128];
__device__ __align__(16) __half g_wet[128 * 128];
__device__ __align__(16) __half g_w1t[9 * 256 * 128];
__device__ __align__(16) __half g_w2t[3 * 128 * 256];
__device__ __align__(16) __half g_wut[3 * 128 * 256];
// sorting scratch
__device__ int g_cnt[NMAX];     // histogram, then cursor
__device__ int g_off[NMAX];
__device__ int g_bsum[128];
__device__ int g_perm[N_EDGES];

__device__ __forceinline__ uint32_t s2u(const void* p) {
    uint32_t a;
    asm("{ .reg .u64 t; cvta.to.shared.u64 t, %1; cvt.u32.u64 %0, t; }" : "=r"(a) : "l"(p));
    return a;
}
__device__ __forceinline__ void ldsm4(uint32_t* r, uint32_t a) {
    asm volatile("ldmatrix.sync.aligned.m8n8.x4.shared.b16 {%0,%1,%2,%3}, [%4];"
        : "=r"(r[0]), "=r"(r[1]), "=r"(r[2]), "=r"(r[3]) : "r"(a));
}
__device__ __forceinline__ void mma16816(float* c, const uint32_t* a, uint32_t b0, uint32_t b1) {
    asm volatile("mma.sync.aligned.m16n8k16.row.col.f32.f16.f16.f32 "
        "{%0,%1,%2,%3},{%4,%5,%6,%7},{%8,%9},{%0,%1,%2,%3};"
        : "+f"(c[0]), "+f"(c[1]), "+f"(c[2]), "+f"(c[3])
        : "r"(a[0]), "r"(a[1]), "r"(a[2]), "r"(a[3]), "r"(b0), "r"(b1));
}
__device__ __forceinline__ float gelu_tanh(float x) {
    const float c = 0.7978845608028654f;
    float t = tanhf(c * (x + 0.044715f * x * x * x));
    return 0.5f * x * (1.0f + t);
}

// ------------- padded-row GEMM core (SA = K*2+16) -------------
template<int K, int NTW>
__device__ __forceinline__ void mma_loop(uint32_t abase, uint32_t bbase,
                                         float (&acc)[2][NTW][4], int wm, int wn, int lane)
{
    const int SA = K * 2 + 16;
    int mat  = lane >> 3;
    int arow = (lane & 7) + ((mat & 1) << 3);
    int akb  = (mat >> 1) << 4;
    int brow = (lane & 7) + ((mat >> 1) << 3);
    int bkb  = (mat & 1) << 4;
    uint32_t a0 = abase + (wm * 32 + arow) * SA + akb;
    uint32_t b0 = bbase + (wn * (8 * NTW) + brow) * SA + bkb;
#pragma unroll
    for (int kt = 0; kt < K / 16; kt++) {
        uint32_t A[2][4], B[NTW / 2][4];
        ldsm4(A[0], a0 + kt * 32);
        ldsm4(A[1], a0 + 16 * SA + kt * 32);
#pragma unroll
        for (int j = 0; j < NTW / 2; j++)
            ldsm4(B[j], b0 + j * 16 * SA + kt * 32);
#pragma unroll
        for (int i = 0; i < 2; i++)
#pragma unroll
            for (int j = 0; j < NTW / 2; j++) {
                mma16816(acc[i][2 * j],     A[i], B[j][0], B[j][1]);
                mma16816(acc[i][2 * j + 1], A[i], B[j][2], B[j][3]);
            }
    }
}

template<int K>
__device__ __forceinline__ void stage_rows(char* dst, const __half* src, size_t row0, int M)
{
    const int SA = K * 2 + 16, CH = K / 8;
    for (int i = threadIdx.x; i < 128 * CH; i += 512) {
        int r = i / CH, c = i % CH;
        uint4 v = make_uint4(0, 0, 0, 0);
        if (row0 + r < (size_t)M) v = *(const uint4*)(src + (row0 + r) * K + c * 8);
        *(uint4*)(dst + r * SA + c * 16) = v;
    }
}
template<int K>
__device__ __forceinline__ void stage_w(char* dst, const __half* src, int rows)
{
    const int SA = K * 2 + 16, CH = K / 8;
    for (int i = threadIdx.x; i < rows * CH; i += 512)
        *(uint4*)(dst + (i / CH) * SA + (i % CH) * 16) = ((const uint4*)src)[i];
}

// =====================================================================================
// sorting kernels (counting sort by receiver; run once per launch)
// =====================================================================================
__global__ void hist_kernel(const int* __restrict__ rcv, int E)
{
    for (int e = blockIdx.x * blockDim.x + threadIdx.x; e < E; e += gridDim.x * blockDim.x)
        atomicAdd(&g_cnt[rcv[e]], 1);
}
__global__ void scan1_kernel(int n)
{
    __shared__ int s[1024];
    int i = blockIdx.x * 1024 + threadIdx.x;
    int v = (i < n) ? g_cnt[i] : 0;
    s[threadIdx.x] = v;
    __syncthreads();
    for (int st = 1; st < 1024; st <<= 1) {
        int t = (threadIdx.x >= st) ? s[threadIdx.x - st] : 0;
        __syncthreads();
        s[threadIdx.x] += t;
        __syncthreads();
    }
    if (i < n) g_off[i] = s[threadIdx.x] - v;
    if (threadIdx.x == 1023) g_bsum[blockIdx.x] = s[1023];
}
__global__ void scan2_kernel(int nb)
{
    __shared__ int s[64];
    int v = (threadIdx.x < nb) ? g_bsum[threadIdx.x] : 0;
    s[threadIdx.x] = v;
    __syncthreads();
    for (int st = 1; st < 64; st <<= 1) {
        int t = (threadIdx.x >= st) ? s[threadIdx.x - st] : 0;
        __syncthreads();
        s[threadIdx.x] += t;
        __syncthreads();
    }
    g_bsum[threadIdx.x] = s[threadIdx.x] - v;
}
__global__ void scan3_kernel(int n)
{
    int i = blockIdx.x * 1024 + threadIdx.x;
    if (i < n) {
        int o = g_off[i] + g_bsum[blockIdx.x];
        g_off[i] = o;
        g_cnt[i] = o;   // cursor
    }
}
__global__ void scatter_kernel(const int* __restrict__ rcv, int E)
{
    for (int e = blockIdx.x * blockDim.x + threadIdx.x; e < E; e += gridDim.x * blockDim.x) {
        int pos = atomicAdd(&g_cnt[rcv[e]], 1);
        g_perm[pos] = e;
    }
}

// =====================================================================================
// transpose_all: one launch for all 17 weight transposes (f32 [K][N] -> f16 [N][K])
// =====================================================================================
__global__ void transpose_all(const float* __restrict__ w_node, const float* __restrict__ w_edge,
                              const float* __restrict__ msg_w1, const float* __restrict__ msg_w2,
                              const float* __restrict__ upd_w,
                              __half* __restrict__ wnt, __half* __restrict__ wet,
                              __half* __restrict__ w1t, __half* __restrict__ w2t,
                              __half* __restrict__ wut)
{
    int z = blockIdx.z;
    const float* src; __half* dst; int K, N;
    if (z == 0)      { src = w_node; dst = wnt; K = 128; N = 128; }
    else if (z == 1) { src = w_edge; dst = wet; K = 128; N = 128; }
    else if (z < 11) {
        int j = z - 2, l = j / 3, p = j % 3;
        src = msg_w1 + (size_t)l * 384 * 256 + (size_t)p * 128 * 256;
        dst = w1t + (size_t)j * 32768; K = 128; N = 256;
    } else if (z < 14) {
        int l = z - 11;
        src = msg_w2 + (size_t)l * 256 * 128; dst = w2t + (size_t)l * 32768; K = 256; N = 128;
    } else {
        int l = z - 14;
        src = upd_w + (size_t)l * 256 * 128; dst = wut + (size_t)l * 32768; K = 256; N = 128;
    }
    int k0 = blockIdx.x * 32, n0 = blockIdx.y * 32;
    if (k0 >= K || n0 >= N) return;
    __shared__ float t[32][33];
    int tx = threadIdx.x & 31, ty = threadIdx.x >> 5;
    for (int i = ty; i < 32; i += 8) {
        int k = k0 + i, n = n0 + tx;
        t[i][tx] = (k < K && n < N) ? src[(size_t)k * N + n] : 0.f;
    }
    __syncthreads();
    for (int i = ty; i < 32; i += 8) {
        int n = n0 + i, k = k0 + tx;
        if (n < N && k < K) dst[(size_t)n * K + k] = __float2half(t[tx][i]);
    }
}

// =====================================================================================
// embed: out = LN(gelu(x@W + b)). K=128, N=128.
// =====================================================================================
__global__ __launch_bounds__(512, 1)
void embed_f16(const float* __restrict__ x, const __half* __restrict__ Wt,
               const float* __restrict__ bias,
               const float* __restrict__ lns, const float* __restrict__ lno,
               float* __restrict__ outf, __half* __restrict__ outh, int M)
{
    extern __shared__ char sm[];
    char* Asm = sm;
    char* Bsm = sm + 34816;
    const int tid = threadIdx.x, w = tid >> 5, lane = tid & 31;
    const size_t row0 = (size_t)blockIdx.x * 128;

    for (int i = tid; i < 128 * 16; i += 512) {
        int r = i >> 4, c = i & 15;
        uint32_t o[4] = {0, 0, 0, 0};
        if (row0 + r < (size_t)M) {
            const float* src = x + (row0 + r) * 128 + c * 8;
            float4 a = ((const float4*)src)[0], b = ((const float4*)src)[1];
            __half2 h0 = __floats2half2_rn(a.x, a.y), h1 = __floats2half2_rn(a.z, a.w);
            __half2 h2 = __floats2half2_rn(b.x, b.y), h3 = __floats2half2_rn(b.z, b.w);
            o[0] = *(uint32_t*)&h0; o[1] = *(uint32_t*)&h1; o[2] = *(uint32_t*)&h2; o[3] = *(uint32_t*)&h3;
        }
        *(uint4*)(Asm + r * 272 + c * 16) = *(uint4*)o;
    }
    stage_w<128>(Bsm, Wt, 128);
    __syncthreads();

    float acc[2][4][4] = {};
    mma_loop<128, 4>(s2u(Asm), s2u(Bsm), acc, w >> 2, w & 3, lane);
    __syncthreads();

    float* Csm = (float*)sm;   // 128 x 132
    const int gid = lane >> 2, tig = lane & 3;
    const int rb = (w >> 2) * 32 + gid, cb = (w & 3) * 32 + tig * 2;
#pragma unroll
    for (int i = 0; i < 2; i++)
#pragma unroll
        for (int nt = 0; nt < 4; nt++) {
            int col = cb + nt * 8;
            int r = rb + i * 16;
            Csm[r * 132 + col]           = gelu_tanh(acc[i][nt][0] + bias[col]);
            Csm[r * 132 + col + 1]       = gelu_tanh(acc[i][nt][1] + bias[col + 1]);
            Csm[(r + 8) * 132 + col]     = gelu_tanh(acc[i][nt][2] + bias[col]);
            Csm[(r + 8) * 132 + col + 1] = gelu_tanh(acc[i][nt][3] + bias[col + 1]);
        }
    __syncthreads();

    int r = tid >> 2, s = tid & 3;
    float4 v[8];
    float sum = 0.f;
#pragma unroll
    for (int k = 0; k < 8; k++) {
        v[k] = *(float4*)&Csm[r * 132 + s * 4 + k * 16];
        sum += v[k].x + v[k].y + v[k].z + v[k].w;
    }
    sum += __shfl_xor_sync(0xffffffffu, sum, 1);
    sum += __shfl_xor_sync(0xffffffffu, sum, 2);
    float mean = sum * (1.0f / 128.0f);
    float q = 0.f;
#pragma unroll
    for (int k = 0; k < 8; k++) {
        float dx = v[k].x - mean, dy = v[k].y - mean, dz = v[k].z - mean, dw = v[k].w - mean;
        q += dx * dx + dy * dy + dz * dz + dw * dw;
    }
    q += __shfl_xor_sync(0xffffffffu, q, 1);
    q += __shfl_xor_sync(0xffffffffu, q, 2);
    float rstd = rsqrtf(q * (1.0f / 128.0f) + 1e-5f);

    size_t row = row0 + r;
    if (row < (size_t)M) {
#pragma unroll
        for (int k = 0; k < 8; k++) {
            int col = s * 4 + k * 16;
            float4 sc = *(const float4*)(lns + col), of = *(const float4*)(lno + col);
            float4 o;
            o.x = (v[k].x - mean) * rstd * sc.x + of.x;
            o.y = (v[k].y - mean) * rstd * sc.y + of.y;
            o.z = (v[k].z - mean) * rstd * sc.z + of.z;
            o.w = (v[k].w - mean) * rstd * sc.w + of.w;
            if (outf) *(float4*)(outf + row * 128 + col) = o;
            if (outh) {
                __half2 h0 = __floats2half2_rn(o.x, o.y), h1 = __floats2half2_rn(o.z, o.w);
                ((uint32_t*)(outh + row * 128 + col))[0] = *(uint32_t*)&h0;
                ((uint32_t*)(outh + row * 128 + col))[1] = *(uint32_t*)&h1;
            }
        }
    }
}

// =====================================================================================
// gemm1x2: C1 = A@B1t^T, C2 = A@B2t^T
// =====================================================================================
__global__ __launch_bounds__(512, 1)
void gemm1x2_f16(const __half* __restrict__ A,
                 const __half* __restrict__ B1t, const __half* __restrict__ B2t,
                 __half* __restrict__ C1, __half* __restrict__ C2, int M)
{
    extern __shared__ char sm[];
    char* Asm  = sm;
    char* Bsm1 = sm + 34816;
    char* Bsm2 = sm + 34816 + 69632;
    const int tid = threadIdx.x, w = tid >> 5, lane = tid & 31;
    const size_t row0 = (size_t)blockIdx.x * 128;

    stage_rows<128>(Asm, A, row0, M);
    stage_w<128>(Bsm1, B1t, 256);
    stage_w<128>(Bsm2, B2t, 256);
    __syncthreads();

    const int gid = lane >> 2, tig = lane & 3;
    const int rb = (w >> 2) * 32 + gid, cb = (w & 3) * 64 + tig * 2;

#pragma unroll
    for (int pass = 0; pass < 2; pass++) {
        float acc[2][8][4] = {};
        mma_loop<128, 8>(s2u(Asm), s2u(pass ? Bsm2 : Bsm1), acc, w >> 2, w & 3, lane);
        __half* C = pass ? C2 : C1;
#pragma unroll
        for (int i = 0; i < 2; i++) {
            size_t r = row0 + rb + i * 16;
#pragma unroll
            for (int nt = 0; nt < 8; nt++) {
                int col = cb + nt * 8;
                __half2 h01 = __floats2half2_rn(acc[i][nt][0], acc[i][nt][1]);
                __half2 h23 = __floats2half2_rn(acc[i][nt][2], acc[i][nt][3]);
                if (r < (size_t)M)     *(__half2*)(C + r * 256 + col) = h01;
                if (r + 8 < (size_t)M) *(__half2*)(C + (r + 8) * 256 + col) = h23;
            }
        }
    }
}

// =====================================================================================
// edge_sorted (persistent): per 128-edge block (edges in receiver-sorted order via perm):
//   Pe = eh[perm]@W1c^T (mma1) -> m1 = relu(Pe + Ps[s] + Pr[r] + b1) in place
//   out = m1@W2^T (mma2); Csm = relu(out + b2)
//   segmented suffix reduction over same-receiver rows; segment heads do float4 RED
// smem: pidx/sidx/ridx 2048 | B1 69632 | B2 67584 | WK 67584 = 206848
// =====================================================================================
__global__ __launch_bounds__(512, 1)
void edge_sorted_f16(const __half* __restrict__ eh,
                     const __half* __restrict__ Ps, const __half* __restrict__ Pr,
                     const __half* __restrict__ W1ct, const float* __restrict__ b1,
                     const __half* __restrict__ W2t,  const float* __restrict__ b2,
                     const int* __restrict__ snd, const int* __restrict__ rcv,
                     const int* __restrict__ perm,
                     float* __restrict__ agg, int E)
{
    extern __shared__ char sm[];
    int* pidx = (int*)sm;            // 128
    int* sidx = (int*)(sm + 512);    // 128
    int* ridx = (int*)(sm + 1024);   // 128
    char* B1 = sm + 2048;            // 69632 (256 rows, SA=272)
    char* B2 = sm + 71680;           // 67584 (128 rows, SA=528)
    char* WK = sm + 139264;          // 67584 work region
    const int tid = threadIdx.x, w = tid >> 5, lane = tid & 31;
    const int gid = lane >> 2, tig = lane & 3;

    stage_w<128>(B1, W1ct, 256);
    stage_w<256>(B2, W2t, 128);
    __syncthreads();

    const int nblk = (E + 127) >> 7;
    for (int blk = blockIdx.x; blk < nblk; blk += gridDim.x) {
        const int e0 = blk << 7;
        if (tid < 128) {
            int eg = (e0 + tid < E) ? perm[e0 + tid] : -1;
            pidx[tid] = eg;
            sidx[tid] = (eg >= 0) ? snd[eg] : -1;
            ridx[tid] = (eg >= 0) ? rcv[eg] : -1;
        }
        __syncthreads();

        // stage A_e rows (gathered via pidx), padded SA=272
        for (int i = tid; i < 128 * 16; i += 512) {
            int r = i >> 4, c = i & 15;
            int eg = pidx[r];
            uint4 v = make_uint4(0, 0, 0, 0);
            if (eg >= 0) v = *(const uint4*)(eh + (size_t)eg * 128 + c * 8);
            *(uint4*)(WK + r * 272 + c * 16) = v;
        }
        __syncthreads();

        // ---- mma1: Pe tile (128x256, K=128) ----
        {
            float acc[2][8][4] = {};
            mma_loop<128, 8>(s2u(WK), s2u(B1), acc, w >> 2, w & 3, lane);
            __syncthreads();   // done reading WK as A_e
            const int rb = (w >> 2) * 32 + gid, cb = (w & 3) * 64 + tig * 2;
#pragma unroll
            for (int i = 0; i < 2; i++)
#pragma unroll
                for (int nt = 0; nt < 8; nt++) {
                    int col = cb + nt * 8;
                    int r = rb + i * 16;
                    __half2 h01 = __floats2half2_rn(acc[i][nt][0], acc[i][nt][1]);
                    __half2 h23 = __floats2half2_rn(acc[i][nt][2], acc[i][nt][3]);
                    *(__half2*)(WK + r * 528 + col * 2)       = h01;
                    *(__half2*)(WK + (r + 8) * 528 + col * 2) = h23;
                }
        }
        __syncthreads();

        // ---- gather + add + relu (in place) ----
        for (int i = tid; i < 128 * 32; i += 512) {
            int r = i >> 5, c = i & 31, k0 = c * 8;
            if (pidx[r] >= 0) {
                int sv = sidx[r], rv = ridx[r];
                uint4 pe = *(uint4*)(WK + r * 528 + c * 16);
                uint4 pa = *(const uint4*)(Ps + (size_t)sv * 256 + k0);
                uint4 pb = *(const uint4*)(Pr + (size_t)rv * 256 + k0);
                float bv[8];
                *(float4*)bv       = *(const float4*)(b1 + k0);
                *(float4*)(bv + 4) = *(const float4*)(b1 + k0 + 4);
                uint32_t o[4];
#pragma unroll
                for (int qq = 0; qq < 4; qq++) {
                    float2 fe = __half22float2(((const __half2*)&pe)[qq]);
                    float2 fa = __half22float2(((const __half2*)&pa)[qq]);
                    float2 fb = __half22float2(((const __half2*)&pb)[qq]);
                    float xx = fmaxf(fe.x + fa.x + fb.x + bv[2 * qq], 0.f);
                    float yy = fmaxf(fe.y + fa.y + fb.y + bv[2 * qq + 1], 0.f);
                    __half2 h = __floats2half2_rn(xx, yy);
                    o[qq] = *(uint32_t*)&h;
                }
                *(uint4*)(WK + r * 528 + c * 16) = *(uint4*)o;
            }
        }
        __syncthreads();

        // ---- mma2: out tile (128x128, K=256) ----
        float acc2[2][4][4] = {};
        mma_loop<256, 4>(s2u(WK), s2u(B2), acc2, w >> 2, w & 3, lane);
        __syncthreads();   // done reading WK as m1

        // ---- Csm = relu(out + b2) ----
        float* Csm = (float*)WK;   // 128 x 132 f32
        {
            const int rb = (w >> 2) * 32 + gid, cb = (w & 3) * 32 + tig * 2;
#pragma unroll
            for (int i = 0; i < 2; i++)
#pragma unroll
                for (int nt = 0; nt < 4; nt++) {
                    int col = cb + nt * 8;
                    int r = rb + i * 16;
                    float2 bb = *(const float2*)(b2 + col);
                    Csm[r * 132 + col]           = fmaxf(acc2[i][nt][0] + bb.x, 0.f);
                    Csm[r * 132 + col + 1]       = fmaxf(acc2[i][nt][1] + bb.y, 0.f);
                    Csm[(r + 8) * 132 + col]     = fmaxf(acc2[i][nt][2] + bb.x, 0.f);
                    Csm[(r + 8) * 132 + col + 1] = fmaxf(acc2[i][nt][3] + bb.y, 0.f);
                }
        }
        __syncthreads();

        // ---- segmented suffix reduction over rows (keys = ridx, sorted) ----
        float4* C4 = (float4*)WK;   // row stride 33 float4
#pragma unroll
        for (int s = 1; s < 128; s <<= 1) {
            float4 tmp[8];
            int doadd[8];
#pragma unroll
            for (int it = 0; it < 8; it++) {
                int idx = tid + it * 512;
                int r = idx >> 5, c = idx & 31;
                doadd[it] = (r + s < 128) && (ridx[r] == ridx[r + s]);
                tmp[it] = doadd[it] ? C4[(r + s) * 33 + c] : make_float4(0.f, 0.f, 0.f, 0.f);
            }
            __syncthreads();
#pragma unroll
            for (int it = 0; it < 8; it++) {
                int idx = tid + it * 512;
                int r = idx >> 5, c = idx & 31;
                if (doadd[it]) {
                    float4 v = C4[r * 33 + c];
                    v.x += tmp[it].x; v.y += tmp[it].y; v.z += tmp[it].z; v.w += tmp[it].w;
                    C4[r * 33 + c] = v;
                }
            }
            __syncthreads();
        }

        // ---- segment heads: float4 atomic add ----
        for (int i = tid; i < 128 * 32; i += 512) {
            int r = i >> 5, c = i & 31;
            int rv = ridx[r];
            bool head = (r == 0) || (ridx[r] != ridx[r - 1]);
            if (head && rv >= 0) {
                float4 v = C4[r * 33 + c];
                atomicAdd((float4*)(agg + (size_t)rv * 128 + c * 4), v);
            }
        }
        __syncthreads();   // WK/idx reused next iteration
    }
}

// =====================================================================================
// node_update: upd = LN(concat(nh, agg) @ Wu + b); out = n + upd. K=256, N=128.
// =====================================================================================
__global__ __launch_bounds__(512, 1)
void node_update_f16(const float* __restrict__ nf, const __half* __restrict__ nh,
                     const float* __restrict__ agg, const __half* __restrict__ Wut,
                     const float* __restrict__ bias,
                     const float* __restrict__ lns, const float* __restrict__ lno,
                     float* __restrict__ outf, __half* __restrict__ outh, int M)
{
    extern __shared__ char sm[];
    char* Asm = sm;
    char* Bsm = sm + 67584;
    const int tid = threadIdx.x, w = tid >> 5, lane = tid & 31;
    const size_t row0 = (size_t)blockIdx.x * 128;

    for (int i = tid; i < 128 * 32; i += 512) {
        int r = i >> 5, c = i & 31, k0 = c * 8;
        uint32_t o[4] = {0, 0, 0, 0};
        size_t row = row0 + r;
        if (row < (size_t)M) {
            if (k0 < 128) {
                *(uint4*)o = *(const uint4*)(nh + row * 128 + k0);
            } else {
                const float* src = agg + row * 128 + (k0 - 128);
                float4 a = ((const float4*)src)[0], b = ((const float4*)src)[1];
                __half2 h0 = __floats2half2_rn(a.x, a.y), h1 = __floats2half2_rn(a.z, a.w);
                __half2 h2 = __floats2half2_rn(b.x, b.y), h3 = __floats2half2_rn(b.z, b.w);
                o[0] = *(uint32_t*)&h0; o[1] = *(uint32_t*)&h1; o[2] = *(uint32_t*)&h2; o[3] = *(uint32_t*)&h3;
            }
        }
        *(uint4*)(Asm + r * 528 + c * 16) = *(uint4*)o;
    }
    stage_w<256>(Bsm, Wut, 128);
    __syncthreads();

    float acc[2][4][4] = {};
    mma_loop<256, 4>(s2u(Asm), s2u(Bsm), acc, w >> 2, w & 3, lane);
    __syncthreads();

    float* Csm = (float*)Asm;
    const int gid = lane >> 2, tig = lane & 3;
    const int rb = (w >> 2) * 32 + gid, cb = (w & 3) * 32 + tig * 2;
#pragma unroll
    for (int i = 0; i < 2; i++)
#pragma unroll
        for (int nt = 0; nt < 4; nt++) {
            int col = cb + nt * 8;
            int r = rb + i * 16;
            Csm[r * 132 + col]           = acc[i][nt][0] + bias[col];
            Csm[r * 132 + col + 1]       = acc[i][nt][1] + bias[col + 1];
            Csm[(r + 8) * 132 + col]     = acc[i][nt][2] + bias[col];
            Csm[(r + 8) * 132 + col + 1] = acc[i][nt][3] + bias[col + 1];
        }
    __syncthreads();

    int r = tid >> 2, s = tid & 3;
    float4 v[8];
    float sum = 0.f;
#pragma unroll
    for (int k = 0; k < 8; k++) {
        v[k] = *(float4*)&Csm[r * 132 + s * 4 + k * 16];
        sum += v[k].x + v[k].y + v[k].z + v[k].w;
    }
    sum += __shfl_xor_sync(0xffffffffu, sum, 1);
    sum += __shfl_xor_sync(0xffffffffu, sum, 2);
    float mean = sum * (1.0f / 128.0f);
    float q = 0.f;
#pragma unroll
    for (int k = 0; k < 8; k++) {
        float dx = v[k].x - mean, dy = v[k].y - mean, dz = v[k].z - mean, dw = v[k].w - mean;
        q += dx * dx + dy * dy + dz * dz + dw * dw;
    }
    q += __shfl_xor_sync(0xffffffffu, q, 1);
    q += __shfl_xor_sync(0xffffffffu, q, 2);
    float rstd = rsqrtf(q * (1.0f / 128.0f) + 1e-5f);

    size_t row = row0 + r;
    if (row < (size_t)M) {
#pragma unroll
        for (int k = 0; k < 8; k++) {
            int col = s * 4 + k * 16;
            float4 sc = *(const float4*)(lns + col), of = *(const float4*)(lno + col);
            float4 res = *(const float4*)(nf + row * 128 + col);
            float4 o;
            o.x = res.x + (v[k].x - mean) * rstd * sc.x + of.x;
            o.y = res.y + (v[k].y - mean) * rstd * sc.y + of.y;
            o.z = res.z + (v[k].z - mean) * rstd * sc.z + of.z;
            o.w = res.w + (v[k].w - mean) * rstd * sc.w + of.w;
            if (outf) *(float4*)(outf + row * 128 + col) = o;
            if (outh) {
                __half2 h0 = __floats2half2_rn(o.x, o.y), h1 = __floats2half2_rn(o.z, o.w);
                ((uint32_t*)(outh + row * 128 + col))[0] = *(uint32_t*)&h0;
                ((uint32_t*)(outh + row * 128 + col))[1] = *(uint32_t*)&h1;
            }
        }
    }
}

// =====================================================================================
extern "C" void kernel_launch(void* const* d_in, const int* in_sizes, int n_in,
                              void* d_out, int out_size)
{
    const float* nodes     = (const float*)d_in[0];
    const float* edges     = (const float*)d_in[1];
    const int*   senders   = (const int*)d_in[2];
    const int*   receivers = (const int*)d_in[3];
    const float* w_node    = (const float*)d_in[4];
    const float* b_node    = (const float*)d_in[5];
    const float* w_edge    = (const float*)d_in[6];
    const float* b_edge    = (const float*)d_in[7];
    const float* ln_n_s    = (const float*)d_in[8];
    const float* ln_n_o    = (const float*)d_in[9];
    const float* ln_e_s    = (const float*)d_in[10];
    const float* ln_e_o    = (const float*)d_in[11];
    const float* msg_w1    = (const float*)d_in[12];
    const float* msg_b1    = (const float*)d_in[13];
    const float* msg_w2    = (const float*)d_in[14];
    const float* msg_b2    = (const float*)d_in[15];
    const float* upd_w     = (const float*)d_in[16];
    const float* upd_b     = (const float*)d_in[17];
    const float* ln_s      = (const float*)d_in[18];
    const float* ln_o      = (const float*)d_in[19];

    const int N = in_sizes[0] / D;
    const int E = in_sizes[1] / D;

    int dev = 0, nsm = 148;
    cudaGetDevice(&dev);
    cudaDeviceGetAttribute(&nsm, cudaDevAttrMultiProcessorCount, dev);

    float *pn, *pagg;
    __half *pnh, *peh, *pPs, *pPr, *pwnt, *pwet, *pw1t, *pw2t, *pwut;
    int *pcnt, *pperm;
    cudaGetSymbolAddress((void**)&pn,   g_n);
    cudaGetSymbolAddress((void**)&pagg, g_agg);
    cudaGetSymbolAddress((void**)&pnh,  g_nh);
    cudaGetSymbolAddress((void**)&peh,  g_eh);
    cudaGetSymbolAddress((void**)&pPs,  g_Psh);
    cudaGetSymbolAddress((void**)&pPr,  g_Prh);
    cudaGetSymbolAddress((void**)&pwnt, g_wnt);
    cudaGetSymbolAddress((void**)&pwet, g_wet);
    cudaGetSymbolAddress((void**)&pw1t, g_w1t);
    cudaGetSymbolAddress((void**)&pw2t, g_w2t);
    cudaGetSymbolAddress((void**)&pwut, g_wut);
    cudaGetSymbolAddress((void**)&pcnt, g_cnt);
    cudaGetSymbolAddress((void**)&pperm, g_perm);

    const size_t embed_smem = 69632;
    const size_t g12_smem   = 174080;
    const size_t edge_smem  = 206848;
    const size_t upd_smem   = 135168;

    cudaFuncSetAttribute(embed_f16,       cudaFuncAttributeMaxDynamicSharedMemorySize, (int)embed_smem);
    cudaFuncSetAttribute(gemm1x2_f16,     cudaFuncAttributeMaxDynamicSharedMemorySize, (int)g12_smem);
    cudaFuncSetAttribute(edge_sorted_f16, cudaFuncAttributeMaxDynamicSharedMemorySize, (int)edge_smem);
    cudaFuncSetAttribute(node_update_f16, cudaFuncAttributeMaxDynamicSharedMemorySize, (int)upd_smem);

    // ---- counting sort of edges by receiver (once; reused all 3 layers) ----
    const int scan_blocks = (N + 1023) / 1024;
    cudaMemsetAsync(pcnt, 0, (size_t)N * sizeof(int), 0);
    hist_kernel<<<256, 512>>>(receivers, E);
    scan1_kernel<<<scan_blocks, 1024>>>(N);
    scan2_kernel<<<1, 64>>>(scan_blocks);
    scan3_kernel<<<scan_blocks, 1024>>>(N);
    scatter_kernel<<<256, 512>>>(receivers, E);

    // ---- all weight transposes in one launch ----
    transpose_all<<<dim3(8, 8, 17), 256>>>(w_node, w_edge, msg_w1, msg_w2, upd_w,
                                           pwnt, pwet, pw1t, pw2t, pwut);

    // ---- embeddings ----
    embed_f16<<<(N + 127) / 128, 512, embed_smem>>>(nodes, pwnt, b_node, ln_n_s, ln_n_o, pn, pnh, N);
    embed_f16<<<(E + 127) / 128, 512, embed_smem>>>(edges, pwet, b_edge, ln_e_s, ln_e_o, (float*)nullptr, peh, E);

    // ---- layers ----
    for (int l = 0; l < 3; l++) {
        gemm1x2_f16<<<(N + 127) / 128, 512, g12_smem>>>(
            pnh, pw1t + (size_t)(l * 3 + 0) * 32768, pw1t + (size_t)(l * 3 + 1) * 32768,
            pPs, pPr, N);
        cudaMemsetAsync(pagg, 0, (size_t)N * D * sizeof(float), 0);
        edge_sorted_f16<<<nsm, 512, edge_smem>>>(
            peh, pPs, pPr,
            pw1t + (size_t)(l * 3 + 2) * 32768, msg_b1 + (size_t)l * 256,
            pw2t + (size_t)l * 32768, msg_b2 + (size_t)l * 128,
            senders, receivers, pperm, pagg, E);
        float* nout = (l == 2) ? (float*)d_out : pn;
        __half* nhout = (l == 2) ? (__half*)nullptr : pnh;
        node_update_f16<<<(N + 127) / 128, 512, upd_smem>>>(
            pn, pnh, pagg, pwut + (size_t)l * 32768, upd_b + (size_t)l * 128,
            ln_s + (size_t)l * 128, ln_o + (size_t)l * 128, nout, nhout, N);
    }
}

// round 10
// speedup vs baseline: 1.3279x; 1.3279x over previous
#include <cuda_runtime.h>
#include <cuda_fp16.h>
#include <stdint.h>
#include <math.h>

#define N_NODES 50000
#define N_EDGES 800000
#define D 128
#define H 256

// ---------------- device scratch ----------------
__device__ __align__(16) float  g_n  [(size_t)N_NODES * D];
__device__ __align__(16) __half g_nh [(size_t)N_NODES * D];
__device__ __align__(16) __half g_eh [(size_t)N_EDGES * D];
__device__ __align__(16) __half g_Psh[(size_t)N_NODES * H];
__device__ __align__(16) __half g_Prh[(size_t)N_NODES * H];
__device__ __align__(16) float  g_agg[(size_t)N_NODES * D];
// pre-transposed fp16 weights ([N][K] K-major)
__device__ __align__(16) __half g_wnt[128 * 128];
__device__ __align__(16) __half g_wet[128 * 128];
__device__ __align__(16) __half g_w1t[9 * 256 * 128];
__device__ __align__(16) __half g_w2t[3 * 128 * 256];
__device__ __align__(16) __half g_wut[3 * 128 * 256];

__device__ __forceinline__ uint32_t s2u(const void* p) {
    uint32_t a;
    asm("{ .reg .u64 t; cvta.to.shared.u64 t, %1; cvt.u32.u64 %0, t; }" : "=r"(a) : "l"(p));
    return a;
}
__device__ __forceinline__ void ldsm4(uint32_t* r, uint32_t a) {
    asm volatile("ldmatrix.sync.aligned.m8n8.x4.shared.b16 {%0,%1,%2,%3}, [%4];"
        : "=r"(r[0]), "=r"(r[1]), "=r"(r[2]), "=r"(r[3]) : "r"(a));
}
__device__ __forceinline__ void mma16816(float* c, const uint32_t* a, uint32_t b0, uint32_t b1) {
    asm volatile("mma.sync.aligned.m16n8k16.row.col.f32.f16.f16.f32 "
        "{%0,%1,%2,%3},{%4,%5,%6,%7},{%8,%9},{%0,%1,%2,%3};"
        : "+f"(c[0]), "+f"(c[1]), "+f"(c[2]), "+f"(c[3])
        : "r"(a[0]), "r"(a[1]), "r"(a[2]), "r"(a[3]), "r"(b0), "r"(b1));
}
__device__ __forceinline__ void cpa16(uint32_t smem, const void* g) {
    asm volatile("cp.async.cg.shared.global [%0], [%1], 16;" :: "r"(smem), "l"(g) : "memory");
}
#define CP_COMMIT() asm volatile("cp.async.commit_group;" ::: "memory")
#define CP_WAIT(n)  asm volatile("cp.async.wait_group %0;" :: "n"(n) : "memory")

__device__ __forceinline__ float gelu_tanh(float x) {
    const float c = 0.7978845608028654f;
    float t = tanhf(c * (x + 0.044715f * x * x * x));
    return 0.5f * x * (1.0f + t);
}

// ------------- padded-row GEMM core (SA = K*2+16), 32-row warp tiles -------------
template<int K, int NTW>
__device__ __forceinline__ void mma_loop(uint32_t abase, uint32_t bbase,
                                         float (&acc)[2][NTW][4], int wm, int wn, int lane)
{
    const int SA = K * 2 + 16;
    int mat  = lane >> 3;
    int arow = (lane & 7) + ((mat & 1) << 3);
    int akb  = (mat >> 1) << 4;
    int brow = (lane & 7) + ((mat >> 1) << 3);
    int bkb  = (mat & 1) << 4;
    uint32_t a0 = abase + (wm * 32 + arow) * SA + akb;
    uint32_t b0 = bbase + (wn * (8 * NTW) + brow) * SA + bkb;
#pragma unroll
    for (int kt = 0; kt < K / 16; kt++) {
        uint32_t A[2][4], B[NTW / 2][4];
        ldsm4(A[0], a0 + kt * 32);
        ldsm4(A[1], a0 + 16 * SA + kt * 32);
#pragma unroll
        for (int j = 0; j < NTW / 2; j++)
            ldsm4(B[j], b0 + j * 16 * SA + kt * 32);
#pragma unroll
        for (int i = 0; i < 2; i++)
#pragma unroll
            for (int j = 0; j < NTW / 2; j++) {
                mma16816(acc[i][2 * j],     A[i], B[j][0], B[j][1]);
                mma16816(acc[i][2 * j + 1], A[i], B[j][2], B[j][3]);
            }
    }
}

// ------------- 16-row warp tile core: A padded (stride SA), B swizzled (stride SB) -------------
template<int K, int NTW, int SA, int SB>
__device__ __forceinline__ void mma_loop_16(uint32_t abase, uint32_t bbase,
                                            float (&acc)[NTW][4], int wm, int wn, int lane)
{
    int mat  = lane >> 3;
    int arow = (lane & 7) + ((mat & 1) << 3);
    int akb  = (mat >> 1) << 4;
    int brow = (lane & 7) + ((mat >> 1) << 3);
    int bkb  = (mat & 1) << 4;
    uint32_t a0 = abase + (wm * 16 + arow) * SA + akb;
#pragma unroll
    for (int kt = 0; kt < K / 16; kt++) {
        uint32_t A[4], B[NTW / 2][4];
        ldsm4(A, a0 + kt * 32);
#pragma unroll
        for (int j = 0; j < NTW / 2; j++) {
            uint32_t br = wn * (8 * NTW) + brow + j * 16;
            uint32_t bk = (uint32_t)(bkb + kt * 32);
            ldsm4(B[j], bbase + br * SB + (bk ^ ((br & 7) << 4)));
        }
#pragma unroll
        for (int j = 0; j < NTW / 2; j++) {
            mma16816(acc[2 * j],     A, B[j][0], B[j][1]);
            mma16816(acc[2 * j + 1], A, B[j][2], B[j][3]);
        }
    }
}

template<int K>
__device__ __forceinline__ void stage_rows(char* dst, const __half* src, size_t row0, int M)
{
    const int SA = K * 2 + 16, CH = K / 8;
    for (int i = threadIdx.x; i < 128 * CH; i += 512) {
        int r = i / CH, c = i % CH;
        uint4 v = make_uint4(0, 0, 0, 0);
        if (row0 + r < (size_t)M) v = *(const uint4*)(src + (row0 + r) * K + c * 8);
        *(uint4*)(dst + r * SA + c * 16) = v;
    }
}
template<int K>
__device__ __forceinline__ void stage_w(char* dst, const __half* src, int rows)
{
    const int SA = K * 2 + 16, CH = K / 8;
    for (int i = threadIdx.x; i < rows * CH; i += 512)
        *(uint4*)(dst + (i / CH) * SA + (i % CH) * 16) = ((const uint4*)src)[i];
}

// =====================================================================================
// transpose_all: one launch for all 17 weight transposes (f32 [K][N] -> f16 [N][K])
// =====================================================================================
__global__ void transpose_all(const float* __restrict__ w_node, const float* __restrict__ w_edge,
                              const float* __restrict__ msg_w1, const float* __restrict__ msg_w2,
                              const float* __restrict__ upd_w,
                              __half* __restrict__ wnt, __half* __restrict__ wet,
                              __half* __restrict__ w1t, __half* __restrict__ w2t,
                              __half* __restrict__ wut)
{
    int z = blockIdx.z;
    const float* src; __half* dst; int K, N;
    if (z == 0)      { src = w_node; dst = wnt; K = 128; N = 128; }
    else if (z == 1) { src = w_edge; dst = wet; K = 128; N = 128; }
    else if (z < 11) {
        int j = z - 2, l = j / 3, p = j % 3;
        src = msg_w1 + (size_t)l * 384 * 256 + (size_t)p * 128 * 256;
        dst = w1t + (size_t)j * 32768; K = 128; N = 256;
    } else if (z < 14) {
        int l = z - 11;
        src = msg_w2 + (size_t)l * 256 * 128; dst = w2t + (size_t)l * 32768; K = 256; N = 128;
    } else {
        int l = z - 14;
        src = upd_w + (size_t)l * 256 * 128; dst = wut + (size_t)l * 32768; K = 256; N = 128;
    }
    int k0 = blockIdx.x * 32, n0 = blockIdx.y * 32;
    if (k0 >= K || n0 >= N) return;
    __shared__ float t[32][33];
    int tx = threadIdx.x & 31, ty = threadIdx.x >> 5;
    for (int i = ty; i < 32; i += 8) {
        int k = k0 + i, n = n0 + tx;
        t[i][tx] = (k < K && n < N) ? src[(size_t)k * N + n] : 0.f;
    }
    __syncthreads();
    for (int i = ty; i < 32; i += 8) {
        int n = n0 + i, k = k0 + tx;
        if (n < N && k < K) dst[(size_t)n * K + k] = __float2half(t[tx][i]);
    }
}

// =====================================================================================
// embed: out = LN(gelu(x@W + b)). K=128, N=128.
// =====================================================================================
__global__ __launch_bounds__(512, 1)
void embed_f16(const float* __restrict__ x, const __half* __restrict__ Wt,
               const float* __restrict__ bias,
               const float* __restrict__ lns, const float* __restrict__ lno,
               float* __restrict__ outf, __half* __restrict__ outh, int M)
{
    extern __shared__ char sm[];
    char* Asm = sm;
    char* Bsm = sm + 34816;
    const int tid = threadIdx.x, w = tid >> 5, lane = tid & 31;
    const size_t row0 = (size_t)blockIdx.x * 128;

    for (int i = tid; i < 128 * 16; i += 512) {
        int r = i >> 4, c = i & 15;
        uint32_t o[4] = {0, 0, 0, 0};
        if (row0 + r < (size_t)M) {
            const float* src = x + (row0 + r) * 128 + c * 8;
            float4 a = ((const float4*)src)[0], b = ((const float4*)src)[1];
            __half2 h0 = __floats2half2_rn(a.x, a.y), h1 = __floats2half2_rn(a.z, a.w);
            __half2 h2 = __floats2half2_rn(b.x, b.y), h3 = __floats2half2_rn(b.z, b.w);
            o[0] = *(uint32_t*)&h0; o[1] = *(uint32_t*)&h1; o[2] = *(uint32_t*)&h2; o[3] = *(uint32_t*)&h3;
        }
        *(uint4*)(Asm + r * 272 + c * 16) = *(uint4*)o;
    }
    stage_w<128>(Bsm, Wt, 128);
    __syncthreads();

    float acc[2][4][4] = {};
    mma_loop<128, 4>(s2u(Asm), s2u(Bsm), acc, w >> 2, w & 3, lane);
    __syncthreads();

    float* Csm = (float*)sm;   // 128 x 132
    const int gid = lane >> 2, tig = lane & 3;
    const int rb = (w >> 2) * 32 + gid, cb = (w & 3) * 32 + tig * 2;
#pragma unroll
    for (int i = 0; i < 2; i++)
#pragma unroll
        for (int nt = 0; nt < 4; nt++) {
            int col = cb + nt * 8;
            int r = rb + i * 16;
            Csm[r * 132 + col]           = gelu_tanh(acc[i][nt][0] + bias[col]);
            Csm[r * 132 + col + 1]       = gelu_tanh(acc[i][nt][1] + bias[col + 1]);
            Csm[(r + 8) * 132 + col]     = gelu_tanh(acc[i][nt][2] + bias[col]);
            Csm[(r + 8) * 132 + col + 1] = gelu_tanh(acc[i][nt][3] + bias[col + 1]);
        }
    __syncthreads();

    int r = tid >> 2, s = tid & 3;
    float4 v[8];
    float sum = 0.f;
#pragma unroll
    for (int k = 0; k < 8; k++) {
        v[k] = *(float4*)&Csm[r * 132 + s * 4 + k * 16];
        sum += v[k].x + v[k].y + v[k].z + v[k].w;
    }
    sum += __shfl_xor_sync(0xffffffffu, sum, 1);
    sum += __shfl_xor_sync(0xffffffffu, sum, 2);
    float mean = sum * (1.0f / 128.0f);
    float q = 0.f;
#pragma unroll
    for (int k = 0; k < 8; k++) {
        float dx = v[k].x - mean, dy = v[k].y - mean, dz = v[k].z - mean, dw = v[k].w - mean;
        q += dx * dx + dy * dy + dz * dz + dw * dw;
    }
    q += __shfl_xor_sync(0xffffffffu, q, 1);
    q += __shfl_xor_sync(0xffffffffu, q, 2);
    float rstd = rsqrtf(q * (1.0f / 128.0f) + 1e-5f);

    size_t row = row0 + r;
    if (row < (size_t)M) {
#pragma unroll
        for (int k = 0; k < 8; k++) {
            int col = s * 4 + k * 16;
            float4 sc = *(const float4*)(lns + col), of = *(const float4*)(lno + col);
            float4 o;
            o.x = (v[k].x - mean) * rstd * sc.x + of.x;
            o.y = (v[k].y - mean) * rstd * sc.y + of.y;
            o.z = (v[k].z - mean) * rstd * sc.z + of.z;
            o.w = (v[k].w - mean) * rstd * sc.w + of.w;
            if (outf) *(float4*)(outf + row * 128 + col) = o;
            if (outh) {
                __half2 h0 = __floats2half2_rn(o.x, o.y), h1 = __floats2half2_rn(o.z, o.w);
                ((uint32_t*)(outh + row * 128 + col))[0] = *(uint32_t*)&h0;
                ((uint32_t*)(outh + row * 128 + col))[1] = *(uint32_t*)&h1;
            }
        }
    }
}

// =====================================================================================
// gemm1x2: C1 = A@B1t^T, C2 = A@B2t^T
// =====================================================================================
__global__ __launch_bounds__(512, 1)
void gemm1x2_f16(const __half* __restrict__ A,
                 const __half* __restrict__ B1t, const __half* __restrict__ B2t,
                 __half* __restrict__ C1, __half* __restrict__ C2, int M)
{
    extern __shared__ char sm[];
    char* Asm  = sm;
    char* Bsm1 = sm + 34816;
    char* Bsm2 = sm + 34816 + 69632;
    const int tid = threadIdx.x, w = tid >> 5, lane = tid & 31;
    const size_t row0 = (size_t)blockIdx.x * 128;

    stage_rows<128>(Asm, A, row0, M);
    stage_w<128>(Bsm1, B1t, 256);
    stage_w<128>(Bsm2, B2t, 256);
    __syncthreads();

    const int gid = lane >> 2, tig = lane & 3;
    const int rb = (w >> 2) * 32 + gid, cb = (w & 3) * 64 + tig * 2;

#pragma unroll
    for (int pass = 0; pass < 2; pass++) {
        float acc[2][8][4] = {};
        mma_loop<128, 8>(s2u(Asm), s2u(pass ? Bsm2 : Bsm1), acc, w >> 2, w & 3, lane);
        __half* C = pass ? C2 : C1;
#pragma unroll
        for (int i = 0; i < 2; i++) {
            size_t r = row0 + rb + i * 16;
#pragma unroll
            for (int nt = 0; nt < 8; nt++) {
                int col = cb + nt * 8;
                __half2 h01 = __floats2half2_rn(acc[i][nt][0], acc[i][nt][1]);
                __half2 h23 = __floats2half2_rn(acc[i][nt][2], acc[i][nt][3]);
                if (r < (size_t)M)     *(__half2*)(C + r * 256 + col) = h01;
                if (r + 8 < (size_t)M) *(__half2*)(C + (r + 8) * 256 + col) = h23;
            }
        }
    }
}

// =====================================================================================
// edge_cp: persistent, 64-edge tiles, cp.async-pipelined gather.
//   group0: A_e tile; group1: raw Ps[s], Pr[r] rows (swizzled buffers)
//   wait(1) -> mma1 overlaps group1 -> wait(0) -> m1 = relu(Pe + PS + PR + b1)
//   -> mma2 -> Csm = relu(+b2) -> float4 RED scatter
// smem: sidx 256 | ridx 256 | b1s 1024 | B1 65536 | B2 65536 | WK 33792 | PS 32768 | PR 32768
//       = 231936 bytes
// =====================================================================================
__global__ __launch_bounds__(512, 1)
void edge_cp_f16(const __half* __restrict__ eh,
                 const __half* __restrict__ Ps, const __half* __restrict__ Pr,
                 const __half* __restrict__ W1ct, const float* __restrict__ b1,
                 const __half* __restrict__ W2t,  const float* __restrict__ b2,
                 const int* __restrict__ snd, const int* __restrict__ rcv,
                 float* __restrict__ agg, int E)
{
    extern __shared__ char sm[];
    int*   sidx = (int*)sm;            // 64
    int*   ridx = (int*)(sm + 256);    // 64
    float* b1s  = (float*)(sm + 512);  // 256
    char* B1 = sm + 1536;              // 65536 (256 rows x 256B, swizzled)
    char* B2 = sm + 67072;             // 65536 (128 rows x 512B, swizzled)
    char* WK = sm + 132608;            // 33792 (A_e @272 then m1/Csm @528/132f)
    char* PS = sm + 166400;            // 32768 (64 rows x 512B, swizzled)
    char* PR = sm + 199168;            // 32768
    const int tid = threadIdx.x, w = tid >> 5, lane = tid & 31;
    const int wm = w >> 2, wn = w & 3;
    const int gid = lane >> 2, tig = lane & 3;
    const uint32_t wk_u = s2u(WK), b1_u = s2u(B1), b2_u = s2u(B2);
    const uint32_t ps_u = s2u(PS), pr_u = s2u(PR);

    // stage weights (swizzled) + b1
    for (int i = tid; i < 256 * 16; i += 512) {
        int r = i >> 4, c = i & 15;
        *(uint4*)(B1 + r * 256 + (((uint32_t)c * 16) ^ ((r & 7) << 4))) =
            *(const uint4*)(W1ct + (size_t)r * 128 + c * 8);
    }
    for (int i = tid; i < 128 * 32; i += 512) {
        int r = i >> 5, c = i & 31;
        *(uint4*)(B2 + r * 512 + (((uint32_t)c * 16) ^ ((r & 7) << 4))) =
            *(const uint4*)(W2t + (size_t)r * 256 + c * 8);
    }
    if (tid < 256) b1s[tid] = b1[tid];
    __syncthreads();

    const int nblk = (E + 63) >> 6;
    for (int blk = blockIdx.x; blk < nblk; blk += gridDim.x) {
        const int e0 = blk << 6;
        if (tid < 64) {
            int eg = e0 + tid;
            sidx[tid] = (eg < E) ? snd[eg] : -1;
            ridx[tid] = (eg < E) ? rcv[eg] : -1;
        }
        __syncthreads();

        // group0: A_e (64 x 128 f16, padded 272)
        for (int i = tid; i < 1024; i += 512) {
            int r = i >> 4, c = i & 15;
            int eg = e0 + r;
            const void* src = eh + (size_t)((eg < E) ? eg : 0) * 128 + c * 8;
            cpa16(wk_u + r * 272 + c * 16, src);
        }
        CP_COMMIT();
        // group1: PS / PR rows (64 x 256 f16 each, swizzled 512)
        for (int i = tid; i < 2048; i += 512) {
            int r = i >> 5, c = i & 31;
            int sv = sidx[r];
            const void* src = Ps + (size_t)((sv < 0) ? 0 : sv) * 256 + c * 8;
            cpa16(ps_u + r * 512 + (((uint32_t)c * 16) ^ ((r & 7) << 4)), src);
        }
        for (int i = tid; i < 2048; i += 512) {
            int r = i >> 5, c = i & 31;
            int rv = ridx[r];
            const void* src = Pr + (size_t)((rv < 0) ? 0 : rv) * 256 + c * 8;
            cpa16(pr_u + r * 512 + (((uint32_t)c * 16) ^ ((r & 7) << 4)), src);
        }
        CP_COMMIT();

        CP_WAIT(1);      // A_e ready; PS/PR still streaming
        __syncthreads();

        // mma1: Pe = A_e @ W1c^T  (64x256, K=128), overlaps PS/PR loads
        float acc1[8][4] = {};
        mma_loop_16<128, 8, 272, 256>(wk_u, b1_u, acc1, wm, wn, lane);

        CP_WAIT(0);      // PS/PR complete
        __syncthreads(); // ...and visible to all; all warps done reading A_e

        // combine: m1 = relu(Pe + PS + PR + b1) -> WK (stride 528)
#pragma unroll
        for (int nt = 0; nt < 8; nt++) {
            int c = wn * 64 + nt * 8 + tig * 2;
            float bx = b1s[c], by = b1s[c + 1];
#pragma unroll
            for (int hh = 0; hh < 2; hh++) {
                int r = wm * 16 + gid + hh * 8;
                uint32_t off = r * 512 + (((uint32_t)c * 2) ^ ((r & 7) << 4));
                float2 fa = __half22float2(*(__half2*)(PS + off));
                float2 fb = __half22float2(*(__half2*)(PR + off));
                float xx = fmaxf(acc1[nt][2 * hh]     + fa.x + fb.x + bx, 0.f);
                float yy = fmaxf(acc1[nt][2 * hh + 1] + fa.y + fb.y + by, 0.f);
                *(__half2*)(WK + r * 528 + c * 2) = __floats2half2_rn(xx, yy);
            }
        }
        __syncthreads();

        // mma2: out = m1 @ W2^T  (64x128, K=256)
        float acc2[4][4] = {};
        mma_loop_16<256, 4, 528, 512>(wk_u, b2_u, acc2, wm, wn, lane);
        __syncthreads();   // all reads of m1 done before Csm overwrites WK

        float* Csm = (float*)WK;   // 64 x 132 f32
#pragma unroll
        for (int nt = 0; nt < 4; nt++) {
            int c = wn * 32 + nt * 8 + tig * 2;
            float2 bb = *(const float2*)(b2 + c);
#pragma unroll
            for (int hh = 0; hh < 2; hh++) {
                int r = wm * 16 + gid + hh * 8;
                Csm[r * 132 + c]     = fmaxf(acc2[nt][2 * hh]     + bb.x, 0.f);
                Csm[r * 132 + c + 1] = fmaxf(acc2[nt][2 * hh + 1] + bb.y, 0.f);
            }
        }
        __syncthreads();

        // scatter: float4 RED
        float4* C4 = (float4*)WK;   // row stride 33 float4
        for (int i = tid; i < 2048; i += 512) {
            int r = i >> 5, c4 = i & 31;
            int rv = ridx[r];
            if (rv >= 0)
                atomicAdd((float4*)(agg + (size_t)rv * 128 + c4 * 4), C4[r * 33 + c4]);
        }
        __syncthreads();   // WK/idx reused next iteration
    }
}

// =====================================================================================
// node_update: upd = LN(concat(nh, agg) @ Wu + b); out = n + upd. K=256, N=128.
// =====================================================================================
__global__ __launch_bounds__(512, 1)
void node_update_f16(const float* __restrict__ nf, const __half* __restrict__ nh,
                     const float* __restrict__ agg, const __half* __restrict__ Wut,
                     const float* __restrict__ bias,
                     const float* __restrict__ lns, const float* __restrict__ lno,
                     float* __restrict__ outf, __half* __restrict__ outh, int M)
{
    extern __shared__ char sm[];
    char* Asm = sm;
    char* Bsm = sm + 67584;
    const int tid = threadIdx.x, w = tid >> 5, lane = tid & 31;
    const size_t row0 = (size_t)blockIdx.x * 128;

    for (int i = tid; i < 128 * 32; i += 512) {
        int r = i >> 5, c = i & 31, k0 = c * 8;
        uint32_t o[4] = {0, 0, 0, 0};
        size_t row = row0 + r;
        if (row < (size_t)M) {
            if (k0 < 128) {
                *(uint4*)o = *(const uint4*)(nh + row * 128 + k0);
            } else {
                const float* src = agg + row * 128 + (k0 - 128);
                float4 a = ((const float4*)src)[0], b = ((const float4*)src)[1];
                __half2 h0 = __floats2half2_rn(a.x, a.y), h1 = __floats2half2_rn(a.z, a.w);
                __half2 h2 = __floats2half2_rn(b.x, b.y), h3 = __floats2half2_rn(b.z, b.w);
                o[0] = *(uint32_t*)&h0; o[1] = *(uint32_t*)&h1; o[2] = *(uint32_t*)&h2; o[3] = *(uint32_t*)&h3;
            }
        }
        *(uint4*)(Asm + r * 528 + c * 16) = *(uint4*)o;
    }
    stage_w<256>(Bsm, Wut, 128);
    __syncthreads();

    float acc[2][4][4] = {};
    mma_loop<256, 4>(s2u(Asm), s2u(Bsm), acc, w >> 2, w & 3, lane);
    __syncthreads();

    float* Csm = (float*)Asm;
    const int gid = lane >> 2, tig = lane & 3;
    const int rb = (w >> 2) * 32 + gid, cb = (w & 3) * 32 + tig * 2;
#pragma unroll
    for (int i = 0; i < 2; i++)
#pragma unroll
        for (int nt = 0; nt < 4; nt++) {
            int col = cb + nt * 8;
            int r = rb + i * 16;
            Csm[r * 132 + col]           = acc[i][nt][0] + bias[col];
            Csm[r * 132 + col + 1]       = acc[i][nt][1] + bias[col + 1];
            Csm[(r + 8) * 132 + col]     = acc[i][nt][2] + bias[col];
            Csm[(r + 8) * 132 + col + 1] = acc[i][nt][3] + bias[col + 1];
        }
    __syncthreads();

    int r = tid >> 2, s = tid & 3;
    float4 v[8];
    float sum = 0.f;
#pragma unroll
    for (int k = 0; k < 8; k++) {
        v[k] = *(float4*)&Csm[r * 132 + s * 4 + k * 16];
        sum += v[k].x + v[k].y + v[k].z + v[k].w;
    }
    sum += __shfl_xor_sync(0xffffffffu, sum, 1);
    sum += __shfl_xor_sync(0xffffffffu, sum, 2);
    float mean = sum * (1.0f / 128.0f);
    float q = 0.f;
#pragma unroll
    for (int k = 0; k < 8; k++) {
        float dx = v[k].x - mean, dy = v[k].y - mean, dz = v[k].z - mean, dw = v[k].w - mean;
        q += dx * dx + dy * dy + dz * dz + dw * dw;
    }
    q += __shfl_xor_sync(0xffffffffu, q, 1);
    q += __shfl_xor_sync(0xffffffffu, q, 2);
    float rstd = rsqrtf(q * (1.0f / 128.0f) + 1e-5f);

    size_t row = row0 + r;
    if (row < (size_t)M) {
#pragma unroll
        for (int k = 0; k < 8; k++) {
            int col = s * 4 + k * 16;
            float4 sc = *(const float4*)(lns + col), of = *(const float4*)(lno + col);
            float4 res = *(const float4*)(nf + row * 128 + col);
            float4 o;
            o.x = res.x + (v[k].x - mean) * rstd * sc.x + of.x;
            o.y = res.y + (v[k].y - mean) * rstd * sc.y + of.y;
            o.z = res.z + (v[k].z - mean) * rstd * sc.z + of.z;
            o.w = res.w + (v[k].w - mean) * rstd * sc.w + of.w;
            if (outf) *(float4*)(outf + row * 128 + col) = o;
            if (outh) {
                __half2 h0 = __floats2half2_rn(o.x, o.y), h1 = __floats2half2_rn(o.z, o.w);
                ((uint32_t*)(outh + row * 128 + col))[0] = *(uint32_t*)&h0;
                ((uint32_t*)(outh + row * 128 + col))[1] = *(uint32_t*)&h1;
            }
        }
    }
}

// =====================================================================================
extern "C" void kernel_launch(void* const* d_in, const int* in_sizes, int n_in,
                              void* d_out, int out_size)
{
    const float* nodes     = (const float*)d_in[0];
    const float* edges     = (const float*)d_in[1];
    const int*   senders   = (const int*)d_in[2];
    const int*   receivers = (const int*)d_in[3];
    const float* w_node    = (const float*)d_in[4];
    const float* b_node    = (const float*)d_in[5];
    const float* w_edge    = (const float*)d_in[6];
    const float* b_edge    = (const float*)d_in[7];
    const float* ln_n_s    = (const float*)d_in[8];
    const float* ln_n_o    = (const float*)d_in[9];
    const float* ln_e_s    = (const float*)d_in[10];
    const float* ln_e_o    = (const float*)d_in[11];
    const float* msg_w1    = (const float*)d_in[12];
    const float* msg_b1    = (const float*)d_in[13];
    const float* msg_w2    = (const float*)d_in[14];
    const float* msg_b2    = (const float*)d_in[15];
    const float* upd_w     = (const float*)d_in[16];
    const float* upd_b     = (const float*)d_in[17];
    const float* ln_s      = (const float*)d_in[18];
    const float* ln_o      = (const float*)d_in[19];

    const int N = in_sizes[0] / D;
    const int E = in_sizes[1] / D;

    int dev = 0, nsm = 148;
    cudaGetDevice(&dev);
    cudaDeviceGetAttribute(&nsm, cudaDevAttrMultiProcessorCount, dev);

    float *pn, *pagg;
    __half *pnh, *peh, *pPs, *pPr, *pwnt, *pwet, *pw1t, *pw2t, *pwut;
    cudaGetSymbolAddress((void**)&pn,   g_n);
    cudaGetSymbolAddress((void**)&pagg, g_agg);
    cudaGetSymbolAddress((void**)&pnh,  g_nh);
    cudaGetSymbolAddress((void**)&peh,  g_eh);
    cudaGetSymbolAddress((void**)&pPs,  g_Psh);
    cudaGetSymbolAddress((void**)&pPr,  g_Prh);
    cudaGetSymbolAddress((void**)&pwnt, g_wnt);
    cudaGetSymbolAddress((void**)&pwet, g_wet);
    cudaGetSymbolAddress((void**)&pw1t, g_w1t);
    cudaGetSymbolAddress((void**)&pw2t, g_w2t);
    cudaGetSymbolAddress((void**)&pwut, g_wut);

    const size_t embed_smem = 69632;
    const size_t g12_smem   = 174080;
    const size_t edge_smem  = 231936;
    const size_t upd_smem   = 135168;

    cudaFuncSetAttribute(embed_f16,       cudaFuncAttributeMaxDynamicSharedMemorySize, (int)embed_smem);
    cudaFuncSetAttribute(gemm1x2_f16,     cudaFuncAttributeMaxDynamicSharedMemorySize, (int)g12_smem);
    cudaFuncSetAttribute(edge_cp_f16,     cudaFuncAttributeMaxDynamicSharedMemorySize, (int)edge_smem);
    cudaFuncSetAttribute(node_update_f16, cudaFuncAttributeMaxDynamicSharedMemorySize, (int)upd_smem);

    // ---- all weight transposes in one launch ----
    transpose_all<<<dim3(8, 8, 17), 256>>>(w_node, w_edge, msg_w1, msg_w2, upd_w,
                                           pwnt, pwet, pw1t, pw2t, pwut);

    // ---- embeddings ----
    embed_f16<<<(N + 127) / 128, 512, embed_smem>>>(nodes, pwnt, b_node, ln_n_s, ln_n_o, pn, pnh, N);
    embed_f16<<<(E + 127) / 128, 512, embed_smem>>>(edges, pwet, b_edge, ln_e_s, ln_e_o, (float*)nullptr, peh, E);

    // ---- layers ----
    for (int l = 0; l < 3; l++) {
        gemm1x2_f16<<<(N + 127) / 128, 512, g12_smem>>>(
            pnh, pw1t + (size_t)(l * 3 + 0) * 32768, pw1t + (size_t)(l * 3 + 1) * 32768,
            pPs, pPr, N);
        cudaMemsetAsync(pagg, 0, (size_t)N * D * sizeof(float), 0);
        edge_cp_f16<<<nsm, 512, edge_smem>>>(
            peh, pPs, pPr,
            pw1t + (size_t)(l * 3 + 2) * 32768, msg_b1 + (size_t)l * 256,
            pw2t + (size_t)l * 32768, msg_b2 + (size_t)l * 128,
            senders, receivers, pagg, E);
        float* nout = (l == 2) ? (float*)d_out : pn;
        __half* nhout = (l == 2) ? (__half*)nullptr : pnh;
        node_update_f16<<<(N + 127) / 128, 512, upd_smem>>>(
            pn, pnh, pagg, pwut + (size_t)l * 32768, upd_b + (size_t)l * 128,
            ln_s + (size_t)l * 128, ln_o + (size_t)l * 128, nout, nhout, N);
    }
}

// round 11
// speedup vs baseline: 1.4709x; 1.1077x over previous
#include <cuda_runtime.h>
#include <cuda_fp16.h>
#include <stdint.h>
#include <math.h>

#define N_NODES 50000
#define N_EDGES 800000
#define D 128
#define H 256

// ---------------- device scratch ----------------
__device__ __align__(16) float  g_n  [(size_t)N_NODES * D];
__device__ __align__(16) __half g_nh [(size_t)N_NODES * D];
__device__ __align__(16) __half g_eh [(size_t)N_EDGES * D];
__device__ __align__(16) __half g_Psh[(size_t)N_NODES * H];
__device__ __align__(16) __half g_Prh[(size_t)N_NODES * H];
__device__ __align__(16) float  g_agg[(size_t)N_NODES * D];
// pre-transposed fp16 weights ([N][K] K-major)
__device__ __align__(16) __half g_wnt[128 * 128];
__device__ __align__(16) __half g_wet[128 * 128];
__device__ __align__(16) __half g_w1t[9 * 256 * 128];
__device__ __align__(16) __half g_w2t[3 * 128 * 256];
__device__ __align__(16) __half g_wut[3 * 128 * 256];

__device__ __forceinline__ uint32_t s2u(const void* p) {
    uint32_t a;
    asm("{ .reg .u64 t; cvta.to.shared.u64 t, %1; cvt.u32.u64 %0, t; }" : "=r"(a) : "l"(p));
    return a;
}
__device__ __forceinline__ void ldsm4(uint32_t* r, uint32_t a) {
    asm volatile("ldmatrix.sync.aligned.m8n8.x4.shared.b16 {%0,%1,%2,%3}, [%4];"
        : "=r"(r[0]), "=r"(r[1]), "=r"(r[2]), "=r"(r[3]) : "r"(a));
}
__device__ __forceinline__ void mma16816(float* c, const uint32_t* a, uint32_t b0, uint32_t b1) {
    asm volatile("mma.sync.aligned.m16n8k16.row.col.f32.f16.f16.f32 "
        "{%0,%1,%2,%3},{%4,%5,%6,%7},{%8,%9},{%0,%1,%2,%3};"
        : "+f"(c[0]), "+f"(c[1]), "+f"(c[2]), "+f"(c[3])
        : "r"(a[0]), "r"(a[1]), "r"(a[2]), "r"(a[3]), "r"(b0), "r"(b1));
}
__device__ __forceinline__ void cpa16(uint32_t smem, const void* g) {
    asm volatile("cp.async.cg.shared.global [%0], [%1], 16;" :: "r"(smem), "l"(g) : "memory");
}
#define CP_COMMIT() asm volatile("cp.async.commit_group;" ::: "memory")
#define CP_WAIT(n)  asm volatile("cp.async.wait_group %0;" :: "n"(n) : "memory")

__device__ __forceinline__ float gelu_tanh(float x) {
    const float c = 0.7978845608028654f;
    float t = tanhf(c * (x + 0.044715f * x * x * x));
    return 0.5f * x * (1.0f + t);
}

// ------------- padded-row GEMM core (SA = K*2+16), 32-row warp tiles -------------
template<int K, int NTW>
__device__ __forceinline__ void mma_loop(uint32_t abase, uint32_t bbase,
                                         float (&acc)[2][NTW][4], int wm, int wn, int lane)
{
    const int SA = K * 2 + 16;
    int mat  = lane >> 3;
    int arow = (lane & 7) + ((mat & 1) << 3);
    int akb  = (mat >> 1) << 4;
    int brow = (lane & 7) + ((mat >> 1) << 3);
    int bkb  = (mat & 1) << 4;
    uint32_t a0 = abase + (wm * 32 + arow) * SA + akb;
    uint32_t b0 = bbase + (wn * (8 * NTW) + brow) * SA + bkb;
#pragma unroll
    for (int kt = 0; kt < K / 16; kt++) {
        uint32_t A[2][4], B[NTW / 2][4];
        ldsm4(A[0], a0 + kt * 32);
        ldsm4(A[1], a0 + 16 * SA + kt * 32);
#pragma unroll
        for (int j = 0; j < NTW / 2; j++)
            ldsm4(B[j], b0 + j * 16 * SA + kt * 32);
#pragma unroll
        for (int i = 0; i < 2; i++)
#pragma unroll
            for (int j = 0; j < NTW / 2; j++) {
                mma16816(acc[i][2 * j],     A[i], B[j][0], B[j][1]);
                mma16816(acc[i][2 * j + 1], A[i], B[j][2], B[j][3]);
            }
    }
}

// ------------- 16-row warp tile core: A and B both XOR-swizzled -------------
template<int K, int NTW, int SA, int SB>
__device__ __forceinline__ void mma_loop_16sw(uint32_t abase, uint32_t bbase,
                                              float (&acc)[NTW][4], int wm, int wn, int lane)
{
    int mat  = lane >> 3;
    int arow = (lane & 7) + ((mat & 1) << 3);
    int akb  = (mat >> 1) << 4;
    int brow = (lane & 7) + ((mat >> 1) << 3);
    int bkb  = (mat & 1) << 4;
    uint32_t ar = wm * 16 + arow;
    uint32_t sw_a = (ar & 7) << 4;
#pragma unroll
    for (int kt = 0; kt < K / 16; kt++) {
        uint32_t A[4], B[NTW / 2][4];
        uint32_t ak = (uint32_t)(akb + kt * 32);
        ldsm4(A, abase + ar * SA + (ak ^ sw_a));
#pragma unroll
        for (int j = 0; j < NTW / 2; j++) {
            uint32_t br = wn * (8 * NTW) + brow + j * 16;
            uint32_t bk = (uint32_t)(bkb + kt * 32);
            ldsm4(B[j], bbase + br * SB + (bk ^ ((br & 7) << 4)));
        }
#pragma unroll
        for (int j = 0; j < NTW / 2; j++) {
            mma16816(acc[2 * j],     A, B[j][0], B[j][1]);
            mma16816(acc[2 * j + 1], A, B[j][2], B[j][3]);
        }
    }
}

template<int K>
__device__ __forceinline__ void stage_rows(char* dst, const __half* src, size_t row0, int M)
{
    const int SA = K * 2 + 16, CH = K / 8;
    for (int i = threadIdx.x; i < 128 * CH; i += 512) {
        int r = i / CH, c = i % CH;
        uint4 v = make_uint4(0, 0, 0, 0);
        if (row0 + r < (size_t)M) v = *(const uint4*)(src + (row0 + r) * K + c * 8);
        *(uint4*)(dst + r * SA + c * 16) = v;
    }
}
template<int K>
__device__ __forceinline__ void stage_w(char* dst, const __half* src, int rows)
{
    const int SA = K * 2 + 16, CH = K / 8;
    for (int i = threadIdx.x; i < rows * CH; i += 512)
        *(uint4*)(dst + (i / CH) * SA + (i % CH) * 16) = ((const uint4*)src)[i];
}

// =====================================================================================
// transpose_all
// =====================================================================================
__global__ void transpose_all(const float* __restrict__ w_node, const float* __restrict__ w_edge,
                              const float* __restrict__ msg_w1, const float* __restrict__ msg_w2,
                              const float* __restrict__ upd_w,
                              __half* __restrict__ wnt, __half* __restrict__ wet,
                              __half* __restrict__ w1t, __half* __restrict__ w2t,
                              __half* __restrict__ wut)
{
    int z = blockIdx.z;
    const float* src; __half* dst; int K, N;
    if (z == 0)      { src = w_node; dst = wnt; K = 128; N = 128; }
    else if (z == 1) { src = w_edge; dst = wet; K = 128; N = 128; }
    else if (z < 11) {
        int j = z - 2, l = j / 3, p = j % 3;
        src = msg_w1 + (size_t)l * 384 * 256 + (size_t)p * 128 * 256;
        dst = w1t + (size_t)j * 32768; K = 128; N = 256;
    } else if (z < 14) {
        int l = z - 11;
        src = msg_w2 + (size_t)l * 256 * 128; dst = w2t + (size_t)l * 32768; K = 256; N = 128;
    } else {
        int l = z - 14;
        src = upd_w + (size_t)l * 256 * 128; dst = wut + (size_t)l * 32768; K = 256; N = 128;
    }
    int k0 = blockIdx.x * 32, n0 = blockIdx.y * 32;
    if (k0 >= K || n0 >= N) return;
    __shared__ float t[32][33];
    int tx = threadIdx.x & 31, ty = threadIdx.x >> 5;
    for (int i = ty; i < 32; i += 8) {
        int k = k0 + i, n = n0 + tx;
        t[i][tx] = (k < K && n < N) ? src[(size_t)k * N + n] : 0.f;
    }
    __syncthreads();
    for (int i = ty; i < 32; i += 8) {
        int n = n0 + i, k = k0 + tx;
        if (n < N && k < K) dst[(size_t)n * K + k] = __float2half(t[tx][i]);
    }
}

// =====================================================================================
// embed: out = LN(gelu(x@W + b)). K=128, N=128.
// =====================================================================================
__global__ __launch_bounds__(512, 1)
void embed_f16(const float* __restrict__ x, const __half* __restrict__ Wt,
               const float* __restrict__ bias,
               const float* __restrict__ lns, const float* __restrict__ lno,
               float* __restrict__ outf, __half* __restrict__ outh, int M)
{
    extern __shared__ char sm[];
    char* Asm = sm;
    char* Bsm = sm + 34816;
    const int tid = threadIdx.x, w = tid >> 5, lane = tid & 31;
    const size_t row0 = (size_t)blockIdx.x * 128;

    for (int i = tid; i < 128 * 16; i += 512) {
        int r = i >> 4, c = i & 15;
        uint32_t o[4] = {0, 0, 0, 0};
        if (row0 + r < (size_t)M) {
            const float* src = x + (row0 + r) * 128 + c * 8;
            float4 a = ((const float4*)src)[0], b = ((const float4*)src)[1];
            __half2 h0 = __floats2half2_rn(a.x, a.y), h1 = __floats2half2_rn(a.z, a.w);
            __half2 h2 = __floats2half2_rn(b.x, b.y), h3 = __floats2half2_rn(b.z, b.w);
            o[0] = *(uint32_t*)&h0; o[1] = *(uint32_t*)&h1; o[2] = *(uint32_t*)&h2; o[3] = *(uint32_t*)&h3;
        }
        *(uint4*)(Asm + r * 272 + c * 16) = *(uint4*)o;
    }
    stage_w<128>(Bsm, Wt, 128);
    __syncthreads();

    float acc[2][4][4] = {};
    mma_loop<128, 4>(s2u(Asm), s2u(Bsm), acc, w >> 2, w & 3, lane);
    __syncthreads();

    float* Csm = (float*)sm;   // 128 x 132
    const int gid = lane >> 2, tig = lane & 3;
    const int rb = (w >> 2) * 32 + gid, cb = (w & 3) * 32 + tig * 2;
#pragma unroll
    for (int i = 0; i < 2; i++)
#pragma unroll
        for (int nt = 0; nt < 4; nt++) {
            int col = cb + nt * 8;
            int r = rb + i * 16;
            Csm[r * 132 + col]           = gelu_tanh(acc[i][nt][0] + bias[col]);
            Csm[r * 132 + col + 1]       = gelu_tanh(acc[i][nt][1] + bias[col + 1]);
            Csm[(r + 8) * 132 + col]     = gelu_tanh(acc[i][nt][2] + bias[col]);
            Csm[(r + 8) * 132 + col + 1] = gelu_tanh(acc[i][nt][3] + bias[col + 1]);
        }
    __syncthreads();

    int r = tid >> 2, s = tid & 3;
    float4 v[8];
    float sum = 0.f;
#pragma unroll
    for (int k = 0; k < 8; k++) {
        v[k] = *(float4*)&Csm[r * 132 + s * 4 + k * 16];
        sum += v[k].x + v[k].y + v[k].z + v[k].w;
    }
    sum += __shfl_xor_sync(0xffffffffu, sum, 1);
    sum += __shfl_xor_sync(0xffffffffu, sum, 2);
    float mean = sum * (1.0f / 128.0f);
    float q = 0.f;
#pragma unroll
    for (int k = 0; k < 8; k++) {
        float dx = v[k].x - mean, dy = v[k].y - mean, dz = v[k].z - mean, dw = v[k].w - mean;
        q += dx * dx + dy * dy + dz * dz + dw * dw;
    }
    q += __shfl_xor_sync(0xffffffffu, q, 1);
    q += __shfl_xor_sync(0xffffffffu, q, 2);
    float rstd = rsqrtf(q * (1.0f / 128.0f) + 1e-5f);

    size_t row = row0 + r;
    if (row < (size_t)M) {
#pragma unroll
        for (int k = 0; k < 8; k++) {
            int col = s * 4 + k * 16;
            float4 sc = *(const float4*)(lns + col), of = *(const float4*)(lno + col);
            float4 o;
            o.x = (v[k].x - mean) * rstd * sc.x + of.x;
            o.y = (v[k].y - mean) * rstd * sc.y + of.y;
            o.z = (v[k].z - mean) * rstd * sc.z + of.z;
            o.w = (v[k].w - mean) * rstd * sc.w + of.w;
            if (outf) *(float4*)(outf + row * 128 + col) = o;
            if (outh) {
                __half2 h0 = __floats2half2_rn(o.x, o.y), h1 = __floats2half2_rn(o.z, o.w);
                ((uint32_t*)(outh + row * 128 + col))[0] = *(uint32_t*)&h0;
                ((uint32_t*)(outh + row * 128 + col))[1] = *(uint32_t*)&h1;
            }
        }
    }
}

// =====================================================================================
// gemm1x2: C1 = A@B1t^T, C2 = A@B2t^T
// =====================================================================================
__global__ __launch_bounds__(512, 1)
void gemm1x2_f16(const __half* __restrict__ A,
                 const __half* __restrict__ B1t, const __half* __restrict__ B2t,
                 __half* __restrict__ C1, __half* __restrict__ C2, int M)
{
    extern __shared__ char sm[];
    char* Asm  = sm;
    char* Bsm1 = sm + 34816;
    char* Bsm2 = sm + 34816 + 69632;
    const int tid = threadIdx.x, w = tid >> 5, lane = tid & 31;
    const size_t row0 = (size_t)blockIdx.x * 128;

    stage_rows<128>(Asm, A, row0, M);
    stage_w<128>(Bsm1, B1t, 256);
    stage_w<128>(Bsm2, B2t, 256);
    __syncthreads();

    const int gid = lane >> 2, tig = lane & 3;
    const int rb = (w >> 2) * 32 + gid, cb = (w & 3) * 64 + tig * 2;

#pragma unroll
    for (int pass = 0; pass < 2; pass++) {
        float acc[2][8][4] = {};
        mma_loop<128, 8>(s2u(Asm), s2u(pass ? Bsm2 : Bsm1), acc, w >> 2, w & 3, lane);
        __half* C = pass ? C2 : C1;
#pragma unroll
        for (int i = 0; i < 2; i++) {
            size_t r = row0 + rb + i * 16;
#pragma unroll
            for (int nt = 0; nt < 8; nt++) {
                int col = cb + nt * 8;
                __half2 h01 = __floats2half2_rn(acc[i][nt][0], acc[i][nt][1]);
                __half2 h23 = __floats2half2_rn(acc[i][nt][2], acc[i][nt][3]);
                if (r < (size_t)M)     *(__half2*)(C + r * 256 + col) = h01;
                if (r + 8 < (size_t)M) *(__half2*)(C + (r + 8) * 256 + col) = h23;
            }
        }
    }
}

// =====================================================================================
// edge_pipe: persistent, 64-edge tiles, 2-deep cp.async pipeline.
//   iter t: wait idx(t)+A_e(t) [issued t-1] -> issue PS/PR(t) -> issue idx/A_e(t+1)
//           -> mma1 (overlaps PS/PR) -> wait PS/PR -> combine m1 in place over PS
//           -> mma2 -> fragment-direct float2 RED scatter
// smem: sidx 512 | ridx 512 | b1s 1024 | b2s 512 | B1 65536 | B2 65536
//       | AE 2x16384 | PS 32768 | PR 32768 = 231936
// =====================================================================================
__global__ __launch_bounds__(512, 1)
void edge_pipe_f16(const __half* __restrict__ eh,
                   const __half* __restrict__ Ps, const __half* __restrict__ Pr,
                   const __half* __restrict__ W1ct, const float* __restrict__ b1,
                   const __half* __restrict__ W2t,  const float* __restrict__ b2,
                   const int* __restrict__ snd, const int* __restrict__ rcv,
                   float* __restrict__ agg, int E)
{
    extern __shared__ char sm[];
    int*   sidx = (int*)sm;              // [2][64]
    int*   ridx = (int*)(sm + 512);      // [2][64]
    float* b1s  = (float*)(sm + 1024);   // 256
    float* b2s  = (float*)(sm + 2048);   // 128
    char* B1 = sm + 2560;                // 65536 (256 rows x 256B, swizzled)
    char* B2 = sm + 68096;               // 65536 (128 rows x 512B, swizzled)
    char* AE = sm + 133632;              // 2 x 16384 (64 rows x 256B, swizzled)
    char* PSb = sm + 166400;             // 32768 (64 rows x 512B, swizzled); becomes m1
    char* PRb = sm + 199168;             // 32768
    const int tid = threadIdx.x, w = tid >> 5, lane = tid & 31;
    const int wm = w >> 2, wn = w & 3;
    const int gid = lane >> 2, tig = lane & 3;
    const uint32_t sidx_u = s2u(sidx), ridx_u = s2u(ridx);
    const uint32_t ae_u = s2u(AE), ps_u = s2u(PSb), pr_u = s2u(PRb);
    const uint32_t b1_u = s2u(B1), b2_u = s2u(B2);

    // stage weights (swizzled) + biases
    for (int i = tid; i < 256 * 16; i += 512) {
        int r = i >> 4, c = i & 15;
        *(uint4*)(B1 + r * 256 + (((uint32_t)c * 16) ^ ((r & 7) << 4))) =
            *(const uint4*)(W1ct + (size_t)r * 128 + c * 8);
    }
    for (int i = tid; i < 128 * 32; i += 512) {
        int r = i >> 5, c = i & 31;
        *(uint4*)(B2 + r * 512 + (((uint32_t)c * 16) ^ ((r & 7) << 4))) =
            *(const uint4*)(W2t + (size_t)r * 256 + c * 8);
    }
    if (tid < 256) b1s[tid] = b1[tid];
    if (tid >= 256 && tid < 384) b2s[tid - 256] = b2[tid - 256];
    __syncthreads();

    const int nblk = (E + 63) >> 6;
    const int bx = blockIdx.x, gsz = gridDim.x;
    const int T = (nblk > bx) ? ((nblk - bx + gsz - 1) / gsz) : 0;
    if (T <= 0) return;

    const int idx_clamp = ((E - 4) > 0) ? ((E - 4) & ~3) : 0;

    // issue idx + A_e for iteration u (sources clamped -> always valid memory)
    auto issue_idxA = [&](int u) {
        int e0n = (bx + u * gsz) << 6;
        int slot = u & 1;
        if (tid < 16) {
            int off = e0n + tid * 4; if (off > idx_clamp) off = idx_clamp;
            cpa16(sidx_u + slot * 256 + tid * 16, snd + off);
        } else if (tid < 32) {
            int t2 = tid - 16;
            int off = e0n + t2 * 4; if (off > idx_clamp) off = idx_clamp;
            cpa16(ridx_u + slot * 256 + t2 * 16, rcv + off);
        }
        for (int i = tid; i < 1024; i += 512) {
            int r = i >> 4, c = i & 15;
            int eg = e0n + r; if (eg > E - 1) eg = E - 1;
            cpa16(ae_u + slot * 16384 + r * 256 + (((uint32_t)c * 16) ^ ((r & 7) << 4)),
                  eh + (size_t)eg * 128 + c * 8);
        }
    };

    issue_idxA(0);
    CP_COMMIT();

    for (int u = 0; u < T; u++) {
        const int slot = u & 1;
        const int e0 = (bx + u * gsz) << 6;

        CP_WAIT(0);          // idx(u), A_e(u) ready
        __syncthreads();

        // snapshot receiver ids (tail-masked) for scatter
        const int r0 = wm * 16 + gid, r1 = r0 + 8;
        const int rv0 = (e0 + r0 < E) ? ridx[slot * 64 + r0] : -1;
        const int rv1 = (e0 + r1 < E) ? ridx[slot * 64 + r1] : -1;

        // issue PS/PR(u) gathers (G1)
        for (int i = tid; i < 2048; i += 512) {
            int r = i >> 5, c = i & 31;
            int sv = sidx[slot * 64 + r];
            cpa16(ps_u + r * 512 + (((uint32_t)c * 16) ^ ((r & 7) << 4)),
                  Ps + (size_t)sv * 256 + c * 8);
        }
        for (int i = tid; i < 2048; i += 512) {
            int r = i >> 5, c = i & 31;
            int rv = ridx[slot * 64 + r];
            cpa16(pr_u + r * 512 + (((uint32_t)c * 16) ^ ((r & 7) << 4)),
                  Pr + (size_t)rv * 256 + c * 8);
        }
        CP_COMMIT();

        // issue idx/A_e(u+1) (G2) — overlaps rest of this iteration
        if (u + 1 < T) issue_idxA(u + 1);
        CP_COMMIT();

        // mma1: Pe = A_e @ W1c^T (64x256, K=128) — overlaps PS/PR gather
        float acc1[8][4] = {};
        mma_loop_16sw<128, 8, 256, 256>(ae_u + slot * 16384, b1_u, acc1, wm, wn, lane);

        CP_WAIT(1);          // PS/PR(u) done (G2 still streaming)
        __syncthreads();

        // combine: m1 = relu(Pe + PS + PR + b1), written in place over PS
#pragma unroll
        for (int nt = 0; nt < 8; nt++) {
            int c = wn * 64 + nt * 8 + tig * 2;
            float bxv = b1s[c], byv = b1s[c + 1];
#pragma unroll
            for (int hh = 0; hh < 2; hh++) {
                int r = wm * 16 + gid + hh * 8;
                uint32_t off = r * 512 + (((uint32_t)(c * 2)) ^ ((r & 7) << 4));
                float2 fa = __half22float2(*(__half2*)(PSb + off));
                float2 fb = __half22float2(*(__half2*)(PRb + off));
                float xx = fmaxf(acc1[nt][2 * hh]     + fa.x + fb.x + bxv, 0.f);
                float yy = fmaxf(acc1[nt][2 * hh + 1] + fa.y + fb.y + byv, 0.f);
                *(__half2*)(PSb + off) = __floats2half2_rn(xx, yy);
            }
        }
        __syncthreads();

        // mma2: out = m1 @ W2^T (64x128, K=256)
        float acc2[4][4] = {};
        mma_loop_16sw<256, 4, 512, 512>(ps_u, b2_u, acc2, wm, wn, lane);

        // fragment-direct scatter: float2 RED with bias+relu
#pragma unroll
        for (int nt = 0; nt < 4; nt++) {
            int c = wn * 32 + nt * 8 + tig * 2;
            float2 bb = *(float2*)&b2s[c];
            if (rv0 >= 0) {
                float2 v0 = make_float2(fmaxf(acc2[nt][0] + bb.x, 0.f),
                                        fmaxf(acc2[nt][1] + bb.y, 0.f));
                atomicAdd((float2*)(agg + (size_t)rv0 * 128 + c), v0);
            }
            if (rv1 >= 0) {
                float2 v1 = make_float2(fmaxf(acc2[nt][2] + bb.x, 0.f),
                                        fmaxf(acc2[nt][3] + bb.y, 0.f));
                atomicAdd((float2*)(agg + (size_t)rv1 * 128 + c), v1);
            }
        }
        // next iteration's top CP_WAIT(0)+syncthreads orders reuse of PS/PR/idx
    }
}

// =====================================================================================
// node_update: upd = LN(concat(nh, agg) @ Wu + b); out = n + upd. K=256, N=128.
// =====================================================================================
__global__ __launch_bounds__(512, 1)
void node_update_f16(const float* __restrict__ nf, const __half* __restrict__ nh,
                     const float* __restrict__ agg, const __half* __restrict__ Wut,
                     const float* __restrict__ bias,
                     const float* __restrict__ lns, const float* __restrict__ lno,
                     float* __restrict__ outf, __half* __restrict__ outh, int M)
{
    extern __shared__ char sm[];
    char* Asm = sm;
    char* Bsm = sm + 67584;
    const int tid = threadIdx.x, w = tid >> 5, lane = tid & 31;
    const size_t row0 = (size_t)blockIdx.x * 128;

    for (int i = tid; i < 128 * 32; i += 512) {
        int r = i >> 5, c = i & 31, k0 = c * 8;
        uint32_t o[4] = {0, 0, 0, 0};
        size_t row = row0 + r;
        if (row < (size_t)M) {
            if (k0 < 128) {
                *(uint4*)o = *(const uint4*)(nh + row * 128 + k0);
            } else {
                const float* src = agg + row * 128 + (k0 - 128);
                float4 a = ((const float4*)src)[0], b = ((const float4*)src)[1];
                __half2 h0 = __floats2half2_rn(a.x, a.y), h1 = __floats2half2_rn(a.z, a.w);
                __half2 h2 = __floats2half2_rn(b.x, b.y), h3 = __floats2half2_rn(b.z, b.w);
                o[0] = *(uint32_t*)&h0; o[1] = *(uint32_t*)&h1; o[2] = *(uint32_t*)&h2; o[3] = *(uint32_t*)&h3;
            }
        }
        *(uint4*)(Asm + r * 528 + c * 16) = *(uint4*)o;
    }
    stage_w<256>(Bsm, Wut, 128);
    __syncthreads();

    float acc[2][4][4] = {};
    mma_loop<256, 4>(s2u(Asm), s2u(Bsm), acc, w >> 2, w & 3, lane);
    __syncthreads();

    float* Csm = (float*)Asm;
    const int gid = lane >> 2, tig = lane & 3;
    const int rb = (w >> 2) * 32 + gid, cb = (w & 3) * 32 + tig * 2;
#pragma unroll
    for (int i = 0; i < 2; i++)
#pragma unroll
        for (int nt = 0; nt < 4; nt++) {
            int col = cb + nt * 8;
            int r = rb + i * 16;
            Csm[r * 132 + col]           = acc[i][nt][0] + bias[col];
            Csm[r * 132 + col + 1]       = acc[i][nt][1] + bias[col + 1];
            Csm[(r + 8) * 132 + col]     = acc[i][nt][2] + bias[col];
            Csm[(r + 8) * 132 + col + 1] = acc[i][nt][3] + bias[col + 1];
        }
    __syncthreads();

    int r = tid >> 2, s = tid & 3;
    float4 v[8];
    float sum = 0.f;
#pragma unroll
    for (int k = 0; k < 8; k++) {
        v[k] = *(float4*)&Csm[r * 132 + s * 4 + k * 16];
        sum += v[k].x + v[k].y + v[k].z + v[k].w;
    }
    sum += __shfl_xor_sync(0xffffffffu, sum, 1);
    sum += __shfl_xor_sync(0xffffffffu, sum, 2);
    float mean = sum * (1.0f / 128.0f);
    float q = 0.f;
#pragma unroll
    for (int k = 0; k < 8; k++) {
        float dx = v[k].x - mean, dy = v[k].y - mean, dz = v[k].z - mean, dw = v[k].w - mean;
        q += dx * dx + dy * dy + dz * dz + dw * dw;
    }
    q += __shfl_xor_sync(0xffffffffu, q, 1);
    q += __shfl_xor_sync(0xffffffffu, q, 2);
    float rstd = rsqrtf(q * (1.0f / 128.0f) + 1e-5f);

    size_t row = row0 + r;
    if (row < (size_t)M) {
#pragma unroll
        for (int k = 0; k < 8; k++) {
            int col = s * 4 + k * 16;
            float4 sc = *(const float4*)(lns + col), of = *(const float4*)(lno + col);
            float4 res = *(const float4*)(nf + row * 128 + col);
            float4 o;
            o.x = res.x + (v[k].x - mean) * rstd * sc.x + of.x;
            o.y = res.y + (v[k].y - mean) * rstd * sc.y + of.y;
            o.z = res.z + (v[k].z - mean) * rstd * sc.z + of.z;
            o.w = res.w + (v[k].w - mean) * rstd * sc.w + of.w;
            if (outf) *(float4*)(outf + row * 128 + col) = o;
            if (outh) {
                __half2 h0 = __floats2half2_rn(o.x, o.y), h1 = __floats2half2_rn(o.z, o.w);
                ((uint32_t*)(outh + row * 128 + col))[0] = *(uint32_t*)&h0;
                ((uint32_t*)(outh + row * 128 + col))[1] = *(uint32_t*)&h1;
            }
        }
    }
}

// =====================================================================================
extern "C" void kernel_launch(void* const* d_in, const int* in_sizes, int n_in,
                              void* d_out, int out_size)
{
    const float* nodes     = (const float*)d_in[0];
    const float* edges     = (const float*)d_in[1];
    const int*   senders   = (const int*)d_in[2];
    const int*   receivers = (const int*)d_in[3];
    const float* w_node    = (const float*)d_in[4];
    const float* b_node    = (const float*)d_in[5];
    const float* w_edge    = (const float*)d_in[6];
    const float* b_edge    = (const float*)d_in[7];
    const float* ln_n_s    = (const float*)d_in[8];
    const float* ln_n_o    = (const float*)d_in[9];
    const float* ln_e_s    = (const float*)d_in[10];
    const float* ln_e_o    = (const float*)d_in[11];
    const float* msg_w1    = (const float*)d_in[12];
    const float* msg_b1    = (const float*)d_in[13];
    const float* msg_w2    = (const float*)d_in[14];
    const float* msg_b2    = (const float*)d_in[15];
    const float* upd_w     = (const float*)d_in[16];
    const float* upd_b     = (const float*)d_in[17];
    const float* ln_s      = (const float*)d_in[18];
    const float* ln_o      = (const float*)d_in[19];

    const int N = in_sizes[0] / D;
    const int E = in_sizes[1] / D;

    int dev = 0, nsm = 148;
    cudaGetDevice(&dev);
    cudaDeviceGetAttribute(&nsm, cudaDevAttrMultiProcessorCount, dev);

    float *pn, *pagg;
    __half *pnh, *peh, *pPs, *pPr, *pwnt, *pwet, *pw1t, *pw2t, *pwut;
    cudaGetSymbolAddress((void**)&pn,   g_n);
    cudaGetSymbolAddress((void**)&pagg, g_agg);
    cudaGetSymbolAddress((void**)&pnh,  g_nh);
    cudaGetSymbolAddress((void**)&peh,  g_eh);
    cudaGetSymbolAddress((void**)&pPs,  g_Psh);
    cudaGetSymbolAddress((void**)&pPr,  g_Prh);
    cudaGetSymbolAddress((void**)&pwnt, g_wnt);
    cudaGetSymbolAddress((void**)&pwet, g_wet);
    cudaGetSymbolAddress((void**)&pw1t, g_w1t);
    cudaGetSymbolAddress((void**)&pw2t, g_w2t);
    cudaGetSymbolAddress((void**)&pwut, g_wut);

    const size_t embed_smem = 69632;
    const size_t g12_smem   = 174080;
    const size_t edge_smem  = 231936;
    const size_t upd_smem   = 135168;

    cudaFuncSetAttribute(embed_f16,       cudaFuncAttributeMaxDynamicSharedMemorySize, (int)embed_smem);
    cudaFuncSetAttribute(gemm1x2_f16,     cudaFuncAttributeMaxDynamicSharedMemorySize, (int)g12_smem);
    cudaFuncSetAttribute(edge_pipe_f16,   cudaFuncAttributeMaxDynamicSharedMemorySize, (int)edge_smem);
    cudaFuncSetAttribute(node_update_f16, cudaFuncAttributeMaxDynamicSharedMemorySize, (int)upd_smem);

    // ---- all weight transposes in one launch ----
    transpose_all<<<dim3(8, 8, 17), 256>>>(w_node, w_edge, msg_w1, msg_w2, upd_w,
                                           pwnt, pwet, pw1t, pw2t, pwut);

    // ---- embeddings ----
    embed_f16<<<(N + 127) / 128, 512, embed_smem>>>(nodes, pwnt, b_node, ln_n_s, ln_n_o, pn, pnh, N);
    embed_f16<<<(E + 127) / 128, 512, embed_smem>>>(edges, pwet, b_edge, ln_e_s, ln_e_o, (float*)nullptr, peh, E);

    // ---- layers ----
    for (int l = 0; l < 3; l++) {
        gemm1x2_f16<<<(N + 127) / 128, 512, g12_smem>>>(
            pnh, pw1t + (size_t)(l * 3 + 0) * 32768, pw1t + (size_t)(l * 3 + 1) * 32768,
            pPs, pPr, N);
        cudaMemsetAsync(pagg, 0, (size_t)N * D * sizeof(float), 0);
        edge_pipe_f16<<<nsm, 512, edge_smem>>>(
            peh, pPs, pPr,
            pw1t + (size_t)(l * 3 + 2) * 32768, msg_b1 + (size_t)l * 256,
            pw2t + (size_t)l * 32768, msg_b2 + (size_t)l * 128,
            senders, receivers, pagg, E);
        float* nout = (l == 2) ? (float*)d_out : pn;
        __half* nhout = (l == 2) ? (__half*)nullptr : pnh;
        node_update_f16<<<(N + 127) / 128, 512, upd_smem>>>(
            pn, pnh, pagg, pwut + (size_t)l * 32768, upd_b + (size_t)l * 128,
            ln_s + (size_t)l * 128, ln_o + (size_t)l * 128, nout, nhout, N);
    }
}

// round 12
// speedup vs baseline: 1.4791x; 1.0056x over previous
#include <cuda_runtime.h>
#include <cuda_fp16.h>
#include <stdint.h>
#include <math.h>

#define N_NODES 50000
#define N_EDGES 800000
#define D 128
#define H 256

// ---------------- device scratch ----------------
__device__ __align__(16) float  g_n  [(size_t)N_NODES * D];
__device__ __align__(16) __half g_nh [(size_t)N_NODES * D];
__device__ __align__(16) __half g_eh [(size_t)N_EDGES * D];
__device__ __align__(16) __half g_Psh[(size_t)N_NODES * H];
__device__ __align__(16) __half g_Prh[(size_t)N_NODES * H];
__device__ __align__(16) float  g_agg[(size_t)N_NODES * D];
// pre-transposed fp16 weights ([N][K] K-major)
__device__ __align__(16) __half g_wnt[128 * 128];
__device__ __align__(16) __half g_wet[128 * 128];
__device__ __align__(16) __half g_w1t[9 * 256 * 128];
__device__ __align__(16) __half g_w2t[3 * 128 * 256];
__device__ __align__(16) __half g_wut[3 * 128 * 256];

__device__ __forceinline__ uint32_t s2u(const void* p) {
    uint32_t a;
    asm("{ .reg .u64 t; cvta.to.shared.u64 t, %1; cvt.u32.u64 %0, t; }" : "=r"(a) : "l"(p));
    return a;
}
__device__ __forceinline__ void ldsm4(uint32_t* r, uint32_t a) {
    asm volatile("ldmatrix.sync.aligned.m8n8.x4.shared.b16 {%0,%1,%2,%3}, [%4];"
        : "=r"(r[0]), "=r"(r[1]), "=r"(r[2]), "=r"(r[3]) : "r"(a));
}
__device__ __forceinline__ void mma16816(float* c, const uint32_t* a, uint32_t b0, uint32_t b1) {
    asm volatile("mma.sync.aligned.m16n8k16.row.col.f32.f16.f16.f32 "
        "{%0,%1,%2,%3},{%4,%5,%6,%7},{%8,%9},{%0,%1,%2,%3};"
        : "+f"(c[0]), "+f"(c[1]), "+f"(c[2]), "+f"(c[3])
        : "r"(a[0]), "r"(a[1]), "r"(a[2]), "r"(a[3]), "r"(b0), "r"(b1));
}
__device__ __forceinline__ void cpa16(uint32_t smem, const void* g) {
    asm volatile("cp.async.cg.shared.global [%0], [%1], 16;" :: "r"(smem), "l"(g) : "memory");
}
#define CP_COMMIT() asm volatile("cp.async.commit_group;" ::: "memory")
#define CP_WAIT(n)  asm volatile("cp.async.wait_group %0;" :: "n"(n) : "memory")

// fast gelu: tanh via ex2.approx-based __expf (rel err ~1e-6, ~6 instr)
__device__ __forceinline__ float gelu_tanh(float x) {
    const float c = 0.7978845608028654f;
    float y = c * (x + 0.044715f * x * x * x);
    float u = fminf(fmaxf(2.f * y, -30.f), 30.f);
    float e = __expf(u);
    float t = __fdividef(e - 1.f, e + 1.f);
    return 0.5f * x * (1.0f + t);
}

// ------------- padded-row GEMM core (SA = K*2+16), 32-row warp tiles -------------
template<int K, int NTW>
__device__ __forceinline__ void mma_loop(uint32_t abase, uint32_t bbase,
                                         float (&acc)[2][NTW][4], int wm, int wn, int lane)
{
    const int SA = K * 2 + 16;
    int mat  = lane >> 3;
    int arow = (lane & 7) + ((mat & 1) << 3);
    int akb  = (mat >> 1) << 4;
    int brow = (lane & 7) + ((mat >> 1) << 3);
    int bkb  = (mat & 1) << 4;
    uint32_t a0 = abase + (wm * 32 + arow) * SA + akb;
    uint32_t b0 = bbase + (wn * (8 * NTW) + brow) * SA + bkb;
#pragma unroll
    for (int kt = 0; kt < K / 16; kt++) {
        uint32_t A[2][4], B[NTW / 2][4];
        ldsm4(A[0], a0 + kt * 32);
        ldsm4(A[1], a0 + 16 * SA + kt * 32);
#pragma unroll
        for (int j = 0; j < NTW / 2; j++)
            ldsm4(B[j], b0 + j * 16 * SA + kt * 32);
#pragma unroll
        for (int i = 0; i < 2; i++)
#pragma unroll
            for (int j = 0; j < NTW / 2; j++) {
                mma16816(acc[i][2 * j],     A[i], B[j][0], B[j][1]);
                mma16816(acc[i][2 * j + 1], A[i], B[j][2], B[j][3]);
            }
    }
}

// ------------- 16-row warp tile core: A and B both XOR-swizzled -------------
template<int K, int NTW, int SA, int SB>
__device__ __forceinline__ void mma_loop_16sw(uint32_t abase, uint32_t bbase,
                                              float (&acc)[NTW][4], int wm, int wn, int lane)
{
    int mat  = lane >> 3;
    int arow = (lane & 7) + ((mat & 1) << 3);
    int akb  = (mat >> 1) << 4;
    int brow = (lane & 7) + ((mat >> 1) << 3);
    int bkb  = (mat & 1) << 4;
    uint32_t ar = wm * 16 + arow;
    uint32_t sw_a = (ar & 7) << 4;
#pragma unroll
    for (int kt = 0; kt < K / 16; kt++) {
        uint32_t A[4], B[NTW / 2][4];
        uint32_t ak = (uint32_t)(akb + kt * 32);
        ldsm4(A, abase + ar * SA + (ak ^ sw_a));
#pragma unroll
        for (int j = 0; j < NTW / 2; j++) {
            uint32_t br = wn * (8 * NTW) + brow + j * 16;
            uint32_t bk = (uint32_t)(bkb + kt * 32);
            ldsm4(B[j], bbase + br * SB + (bk ^ ((br & 7) << 4)));
        }
#pragma unroll
        for (int j = 0; j < NTW / 2; j++) {
            mma16816(acc[2 * j],     A, B[j][0], B[j][1]);
            mma16816(acc[2 * j + 1], A, B[j][2], B[j][3]);
        }
    }
}

// =====================================================================================
// transpose_all
// =====================================================================================
__global__ void transpose_all(const float* __restrict__ w_node, const float* __restrict__ w_edge,
                              const float* __restrict__ msg_w1, const float* __restrict__ msg_w2,
                              const float* __restrict__ upd_w,
                              __half* __restrict__ wnt, __half* __restrict__ wet,
                              __half* __restrict__ w1t, __half* __restrict__ w2t,
                              __half* __restrict__ wut)
{
    int z = blockIdx.z;
    const float* src; __half* dst; int K, N;
    if (z == 0)      { src = w_node; dst = wnt; K = 128; N = 128; }
    else if (z == 1) { src = w_edge; dst = wet; K = 128; N = 128; }
    else if (z < 11) {
        int j = z - 2, l = j / 3, p = j % 3;
        src = msg_w1 + (size_t)l * 384 * 256 + (size_t)p * 128 * 256;
        dst = w1t + (size_t)j * 32768; K = 128; N = 256;
    } else if (z < 14) {
        int l = z - 11;
        src = msg_w2 + (size_t)l * 256 * 128; dst = w2t + (size_t)l * 32768; K = 256; N = 128;
    } else {
        int l = z - 14;
        src = upd_w + (size_t)l * 256 * 128; dst = wut + (size_t)l * 32768; K = 256; N = 128;
    }
    int k0 = blockIdx.x * 32, n0 = blockIdx.y * 32;
    if (k0 >= K || n0 >= N) return;
    __shared__ float t[32][33];
    int tx = threadIdx.x & 31, ty = threadIdx.x >> 5;
    for (int i = ty; i < 32; i += 8) {
        int k = k0 + i, n = n0 + tx;
        t[i][tx] = (k < K && n < N) ? src[(size_t)k * N + n] : 0.f;
    }
    __syncthreads();
    for (int i = ty; i < 32; i += 8) {
        int n = n0 + i, k = k0 + tx;
        if (n < N && k < K) dst[(size_t)n * K + k] = __float2half(t[tx][i]);
    }
}

// =====================================================================================
// embed: out = LN(gelu(x@W + b)). K=128, N=128. 64 rows/CTA, 256 thr, 2 CTAs/SM.
// smem: A 17408 + W 34816 = 52224 (Csm 64x132 f32 = 33792 overlays)
// =====================================================================================
__global__ __launch_bounds__(256, 2)
void embed_f16(const float* __restrict__ x, const __half* __restrict__ Wt,
               const float* __restrict__ bias,
               const float* __restrict__ lns, const float* __restrict__ lno,
               float* __restrict__ outf, __half* __restrict__ outh, int M)
{
    extern __shared__ char sm[];
    char* Asm = sm;                 // 64 x 272
    char* Bsm = sm + 17408;         // 128 x 272
    const int tid = threadIdx.x, w = tid >> 5, lane = tid & 31;
    const int wm = w >> 2, wn = w & 3;
    const size_t row0 = (size_t)blockIdx.x * 64;

    for (int i = tid; i < 64 * 16; i += 256) {
        int r = i >> 4, c = i & 15;
        uint32_t o[4] = {0, 0, 0, 0};
        if (row0 + r < (size_t)M) {
            const float* src = x + (row0 + r) * 128 + c * 8;
            float4 a = ((const float4*)src)[0], b = ((const float4*)src)[1];
            __half2 h0 = __floats2half2_rn(a.x, a.y), h1 = __floats2half2_rn(a.z, a.w);
            __half2 h2 = __floats2half2_rn(b.x, b.y), h3 = __floats2half2_rn(b.z, b.w);
            o[0] = *(uint32_t*)&h0; o[1] = *(uint32_t*)&h1; o[2] = *(uint32_t*)&h2; o[3] = *(uint32_t*)&h3;
        }
        *(uint4*)(Asm + r * 272 + c * 16) = *(uint4*)o;
    }
    for (int i = tid; i < 128 * 16; i += 256) {
        int r = i >> 4, c = i & 15;
        *(uint4*)(Bsm + r * 272 + c * 16) = *(const uint4*)(Wt + r * 128 + c * 8);
    }
    __syncthreads();

    float acc[2][4][4] = {};
    mma_loop<128, 4>(s2u(Asm), s2u(Bsm), acc, wm, wn, lane);
    __syncthreads();

    float* Csm = (float*)sm;   // 64 x 132
    const int gid = lane >> 2, tig = lane & 3;
    const int rb = wm * 32 + gid, cb = wn * 32 + tig * 2;
#pragma unroll
    for (int i = 0; i < 2; i++)
#pragma unroll
        for (int nt = 0; nt < 4; nt++) {
            int col = cb + nt * 8;
            int r = rb + i * 16;
            Csm[r * 132 + col]           = gelu_tanh(acc[i][nt][0] + bias[col]);
            Csm[r * 132 + col + 1]       = gelu_tanh(acc[i][nt][1] + bias[col + 1]);
            Csm[(r + 8) * 132 + col]     = gelu_tanh(acc[i][nt][2] + bias[col]);
            Csm[(r + 8) * 132 + col + 1] = gelu_tanh(acc[i][nt][3] + bias[col + 1]);
        }
    __syncthreads();

    int r = tid >> 2, s = tid & 3;   // r in [0,64)
    float4 v[8];
    float sum = 0.f;
#pragma unroll
    for (int k = 0; k < 8; k++) {
        v[k] = *(float4*)&Csm[r * 132 + s * 4 + k * 16];
        sum += v[k].x + v[k].y + v[k].z + v[k].w;
    }
    sum += __shfl_xor_sync(0xffffffffu, sum, 1);
    sum += __shfl_xor_sync(0xffffffffu, sum, 2);
    float mean = sum * (1.0f / 128.0f);
    float q = 0.f;
#pragma unroll
    for (int k = 0; k < 8; k++) {
        float dx = v[k].x - mean, dy = v[k].y - mean, dz = v[k].z - mean, dw = v[k].w - mean;
        q += dx * dx + dy * dy + dz * dz + dw * dw;
    }
    q += __shfl_xor_sync(0xffffffffu, q, 1);
    q += __shfl_xor_sync(0xffffffffu, q, 2);
    float rstd = rsqrtf(q * (1.0f / 128.0f) + 1e-5f);

    size_t row = row0 + r;
    if (row < (size_t)M) {
#pragma unroll
        for (int k = 0; k < 8; k++) {
            int col = s * 4 + k * 16;
            float4 sc = *(const float4*)(lns + col), of = *(const float4*)(lno + col);
            float4 o;
            o.x = (v[k].x - mean) * rstd * sc.x + of.x;
            o.y = (v[k].y - mean) * rstd * sc.y + of.y;
            o.z = (v[k].z - mean) * rstd * sc.z + of.z;
            o.w = (v[k].w - mean) * rstd * sc.w + of.w;
            if (outf) *(float4*)(outf + row * 128 + col) = o;
            if (outh) {
                __half2 h0 = __floats2half2_rn(o.x, o.y), h1 = __floats2half2_rn(o.z, o.w);
                ((uint32_t*)(outh + row * 128 + col))[0] = *(uint32_t*)&h0;
                ((uint32_t*)(outh + row * 128 + col))[1] = *(uint32_t*)&h1;
            }
        }
    }
}

// =====================================================================================
// gemm1: C[M,256] = A[M,128] @ Bt[256][128]. 64 rows/CTA, 256 thr, 2 CTAs/SM.
// smem: A 17408 + B 69632 = 87040
// =====================================================================================
__global__ __launch_bounds__(256, 2)
void gemm1_f16(const __half* __restrict__ A, const __half* __restrict__ Bt,
               __half* __restrict__ C, int M)
{
    extern __shared__ char sm[];
    char* Asm = sm;                 // 64 x 272
    char* Bsm = sm + 17408;         // 256 x 272
    const int tid = threadIdx.x, w = tid >> 5, lane = tid & 31;
    const int wm = w >> 2, wn = w & 3;
    const size_t row0 = (size_t)blockIdx.x * 64;

    for (int i = tid; i < 64 * 16; i += 256) {
        int r = i >> 4, c = i & 15;
        uint4 v = make_uint4(0, 0, 0, 0);
        if (row0 + r < (size_t)M) v = *(const uint4*)(A + (row0 + r) * 128 + c * 8);
        *(uint4*)(Asm + r * 272 + c * 16) = v;
    }
    for (int i = tid; i < 256 * 16; i += 256) {
        int r = i >> 4, c = i & 15;
        *(uint4*)(Bsm + r * 272 + c * 16) = *(const uint4*)(Bt + (size_t)r * 128 + c * 8);
    }
    __syncthreads();

    float acc[2][8][4] = {};
    mma_loop<128, 8>(s2u(Asm), s2u(Bsm), acc, wm, wn, lane);

    const int gid = lane >> 2, tig = lane & 3;
    const int rb = wm * 32 + gid, cb = wn * 64 + tig * 2;
#pragma unroll
    for (int i = 0; i < 2; i++) {
        size_t r = row0 + rb + i * 16;
#pragma unroll
        for (int nt = 0; nt < 8; nt++) {
            int col = cb + nt * 8;
            __half2 h01 = __floats2half2_rn(acc[i][nt][0], acc[i][nt][1]);
            __half2 h23 = __floats2half2_rn(acc[i][nt][2], acc[i][nt][3]);
            if (r < (size_t)M)     *(__half2*)(C + r * 256 + col) = h01;
            if (r + 8 < (size_t)M) *(__half2*)(C + (r + 8) * 256 + col) = h23;
        }
    }
}

// =====================================================================================
// edge_pipe: persistent, 64-edge tiles, 2-deep cp.async pipeline. (unchanged from R11)
// =====================================================================================
__global__ __launch_bounds__(512, 1)
void edge_pipe_f16(const __half* __restrict__ eh,
                   const __half* __restrict__ Ps, const __half* __restrict__ Pr,
                   const __half* __restrict__ W1ct, const float* __restrict__ b1,
                   const __half* __restrict__ W2t,  const float* __restrict__ b2,
                   const int* __restrict__ snd, const int* __restrict__ rcv,
                   float* __restrict__ agg, int E)
{
    extern __shared__ char sm[];
    int*   sidx = (int*)sm;              // [2][64]
    int*   ridx = (int*)(sm + 512);      // [2][64]
    float* b1s  = (float*)(sm + 1024);   // 256
    float* b2s  = (float*)(sm + 2048);   // 128
    char* B1 = sm + 2560;                // 65536
    char* B2 = sm + 68096;               // 65536
    char* AE = sm + 133632;              // 2 x 16384
    char* PSb = sm + 166400;             // 32768 (becomes m1)
    char* PRb = sm + 199168;             // 32768
    const int tid = threadIdx.x, w = tid >> 5, lane = tid & 31;
    const int wm = w >> 2, wn = w & 3;
    const int gid = lane >> 2, tig = lane & 3;
    const uint32_t sidx_u = s2u(sidx), ridx_u = s2u(ridx);
    const uint32_t ae_u = s2u(AE), ps_u = s2u(PSb), pr_u = s2u(PRb);
    const uint32_t b1_u = s2u(B1), b2_u = s2u(B2);

    for (int i = tid; i < 256 * 16; i += 512) {
        int r = i >> 4, c = i & 15;
        *(uint4*)(B1 + r * 256 + (((uint32_t)c * 16) ^ ((r & 7) << 4))) =
            *(const uint4*)(W1ct + (size_t)r * 128 + c * 8);
    }
    for (int i = tid; i < 128 * 32; i += 512) {
        int r = i >> 5, c = i & 31;
        *(uint4*)(B2 + r * 512 + (((uint32_t)c * 16) ^ ((r & 7) << 4))) =
            *(const uint4*)(W2t + (size_t)r * 256 + c * 8);
    }
    if (tid < 256) b1s[tid] = b1[tid];
    if (tid >= 256 && tid < 384) b2s[tid - 256] = b2[tid - 256];
    __syncthreads();

    const int nblk = (E + 63) >> 6;
    const int bx = blockIdx.x, gsz = gridDim.x;
    const int T = (nblk > bx) ? ((nblk - bx + gsz - 1) / gsz) : 0;
    if (T <= 0) return;

    const int idx_clamp = ((E - 4) > 0) ? ((E - 4) & ~3) : 0;

    auto issue_idxA = [&](int u) {
        int e0n = (bx + u * gsz) << 6;
        int slot = u & 1;
        if (tid < 16) {
            int off = e0n + tid * 4; if (off > idx_clamp) off = idx_clamp;
            cpa16(sidx_u + slot * 256 + tid * 16, snd + off);
        } else if (tid < 32) {
            int t2 = tid - 16;
            int off = e0n + t2 * 4; if (off > idx_clamp) off = idx_clamp;
            cpa16(ridx_u + slot * 256 + t2 * 16, rcv + off);
        }
        for (int i = tid; i < 1024; i += 512) {
            int r = i >> 4, c = i & 15;
            int eg = e0n + r; if (eg > E - 1) eg = E - 1;
            cpa16(ae_u + slot * 16384 + r * 256 + (((uint32_t)c * 16) ^ ((r & 7) << 4)),
                  eh + (size_t)eg * 128 + c * 8);
        }
    };

    issue_idxA(0);
    CP_COMMIT();

    for (int u = 0; u < T; u++) {
        const int slot = u & 1;
        const int e0 = (bx + u * gsz) << 6;

        CP_WAIT(0);
        __syncthreads();

        const int r0 = wm * 16 + gid, r1 = r0 + 8;
        const int rv0 = (e0 + r0 < E) ? ridx[slot * 64 + r0] : -1;
        const int rv1 = (e0 + r1 < E) ? ridx[slot * 64 + r1] : -1;

        for (int i = tid; i < 2048; i += 512) {
            int r = i >> 5, c = i & 31;
            int sv = sidx[slot * 64 + r];
            cpa16(ps_u + r * 512 + (((uint32_t)c * 16) ^ ((r & 7) << 4)),
                  Ps + (size_t)sv * 256 + c * 8);
        }
        for (int i = tid; i < 2048; i += 512) {
            int r = i >> 5, c = i & 31;
            int rv = ridx[slot * 64 + r];
            cpa16(pr_u + r * 512 + (((uint32_t)c * 16) ^ ((r & 7) << 4)),
                  Pr + (size_t)rv * 256 + c * 8);
        }
        CP_COMMIT();

        if (u + 1 < T) issue_idxA(u + 1);
        CP_COMMIT();

        float acc1[8][4] = {};
        mma_loop_16sw<128, 8, 256, 256>(ae_u + slot * 16384, b1_u, acc1, wm, wn, lane);

        CP_WAIT(1);
        __syncthreads();

#pragma unroll
        for (int nt = 0; nt < 8; nt++) {
            int c = wn * 64 + nt * 8 + tig * 2;
            float bxv = b1s[c], byv = b1s[c + 1];
#pragma unroll
            for (int hh = 0; hh < 2; hh++) {
                int r = wm * 16 + gid + hh * 8;
                uint32_t off = r * 512 + (((uint32_t)(c * 2)) ^ ((r & 7) << 4));
                float2 fa = __half22float2(*(__half2*)(PSb + off));
                float2 fb = __half22float2(*(__half2*)(PRb + off));
                float xx = fmaxf(acc1[nt][2 * hh]     + fa.x + fb.x + bxv, 0.f);
                float yy = fmaxf(acc1[nt][2 * hh + 1] + fa.y + fb.y + byv, 0.f);
                *(__half2*)(PSb + off) = __floats2half2_rn(xx, yy);
            }
        }
        __syncthreads();

        float acc2[4][4] = {};
        mma_loop_16sw<256, 4, 512, 512>(ps_u, b2_u, acc2, wm, wn, lane);

#pragma unroll
        for (int nt = 0; nt < 4; nt++) {
            int c = wn * 32 + nt * 8 + tig * 2;
            float2 bb = *(float2*)&b2s[c];
            if (rv0 >= 0) {
                float2 v0 = make_float2(fmaxf(acc2[nt][0] + bb.x, 0.f),
                                        fmaxf(acc2[nt][1] + bb.y, 0.f));
                atomicAdd((float2*)(agg + (size_t)rv0 * 128 + c), v0);
            }
            if (rv1 >= 0) {
                float2 v1 = make_float2(fmaxf(acc2[nt][2] + bb.x, 0.f),
                                        fmaxf(acc2[nt][3] + bb.y, 0.f));
                atomicAdd((float2*)(agg + (size_t)rv1 * 128 + c), v1);
            }
        }
    }
}

// =====================================================================================
// node_update: upd = LN(concat(nh, agg) @ Wu + b); out = n + upd.
// K=256, N=128. 64 rows/CTA, 256 thr, 2 CTAs/SM. smem: A 33792 + B 67584 = 101376
// =====================================================================================
__global__ __launch_bounds__(256, 2)
void node_update_f16(const float* __restrict__ nf, const __half* __restrict__ nh,
                     const float* __restrict__ agg, const __half* __restrict__ Wut,
                     const float* __restrict__ bias,
                     const float* __restrict__ lns, const float* __restrict__ lno,
                     float* __restrict__ outf, __half* __restrict__ outh, int M)
{
    extern __shared__ char sm[];
    char* Asm = sm;                 // 64 x 528
    char* Bsm = sm + 33792;         // 128 x 528
    const int tid = threadIdx.x, w = tid >> 5, lane = tid & 31;
    const int wm = w >> 2, wn = w & 3;
    const size_t row0 = (size_t)blockIdx.x * 64;

    for (int i = tid; i < 64 * 32; i += 256) {
        int r = i >> 5, c = i & 31, k0 = c * 8;
        uint32_t o[4] = {0, 0, 0, 0};
        size_t row = row0 + r;
        if (row < (size_t)M) {
            if (k0 < 128) {
                *(uint4*)o = *(const uint4*)(nh + row * 128 + k0);
            } else {
                const float* src = agg + row * 128 + (k0 - 128);
                float4 a = ((const float4*)src)[0], b = ((const float4*)src)[1];
                __half2 h0 = __floats2half2_rn(a.x, a.y), h1 = __floats2half2_rn(a.z, a.w);
                __half2 h2 = __floats2half2_rn(b.x, b.y), h3 = __floats2half2_rn(b.z, b.w);
                o[0] = *(uint32_t*)&h0; o[1] = *(uint32_t*)&h1; o[2] = *(uint32_t*)&h2; o[3] = *(uint32_t*)&h3;
            }
        }
        *(uint4*)(Asm + r * 528 + c * 16) = *(uint4*)o;
    }
    for (int i = tid; i < 128 * 32; i += 256) {
        int r = i >> 5, c = i & 31;
        *(uint4*)(Bsm + r * 528 + c * 16) = *(const uint4*)(Wut + (size_t)r * 256 + c * 8);
    }
    __syncthreads();

    float acc[2][4][4] = {};
    mma_loop<256, 4>(s2u(Asm), s2u(Bsm), acc, wm, wn, lane);
    __syncthreads();

    float* Csm = (float*)Asm;   // 64 x 132
    const int gid = lane >> 2, tig = lane & 3;
    const int rb = wm * 32 + gid, cb = wn * 32 + tig * 2;
#pragma unroll
    for (int i = 0; i < 2; i++)
#pragma unroll
        for (int nt = 0; nt < 4; nt++) {
            int col = cb + nt * 8;
            int r = rb + i * 16;
            Csm[r * 132 + col]           = acc[i][nt][0] + bias[col];
            Csm[r * 132 + col + 1]       = acc[i][nt][1] + bias[col + 1];
            Csm[(r + 8) * 132 + col]     = acc[i][nt][2] + bias[col];
            Csm[(r + 8) * 132 + col + 1] = acc[i][nt][3] + bias[col + 1];
        }
    __syncthreads();

    int r = tid >> 2, s = tid & 3;   // r in [0,64)
    float4 v[8];
    float sum = 0.f;
#pragma unroll
    for (int k = 0; k < 8; k++) {
        v[k] = *(float4*)&Csm[r * 132 + s * 4 + k * 16];
        sum += v[k].x + v[k].y + v[k].z + v[k].w;
    }
    sum += __shfl_xor_sync(0xffffffffu, sum, 1);
    sum += __shfl_xor_sync(0xffffffffu, sum, 2);
    float mean = sum * (1.0f / 128.0f);
    float q = 0.f;
#pragma unroll
    for (int k = 0; k < 8; k++) {
        float dx = v[k].x - mean, dy = v[k].y - mean, dz = v[k].z - mean, dw = v[k].w - mean;
        q += dx * dx + dy * dy + dz * dz + dw * dw;
    }
    q += __shfl_xor_sync(0xffffffffu, q, 1);
    q += __shfl_xor_sync(0xffffffffu, q, 2);
    float rstd = rsqrtf(q * (1.0f / 128.0f) + 1e-5f);

    size_t row = row0 + r;
    if (row < (size_t)M) {
#pragma unroll
        for (int k = 0; k < 8; k++) {
            int col = s * 4 + k * 16;
            float4 sc = *(const float4*)(lns + col), of = *(const float4*)(lno + col);
            float4 res = *(const float4*)(nf + row * 128 + col);
            float4 o;
            o.x = res.x + (v[k].x - mean) * rstd * sc.x + of.x;
            o.y = res.y + (v[k].y - mean) * rstd * sc.y + of.y;
            o.z = res.z + (v[k].z - mean) * rstd * sc.z + of.z;
            o.w = res.w + (v[k].w - mean) * rstd * sc.w + of.w;
            if (outf) *(float4*)(outf + row * 128 + col) = o;
            if (outh) {
                __half2 h0 = __floats2half2_rn(o.x, o.y), h1 = __floats2half2_rn(o.z, o.w);
                ((uint32_t*)(outh + row * 128 + col))[0] = *(uint32_t*)&h0;
                ((uint32_t*)(outh + row * 128 + col))[1] = *(uint32_t*)&h1;
            }
        }
    }
}

// =====================================================================================
extern "C" void kernel_launch(void* const* d_in, const int* in_sizes, int n_in,
                              void* d_out, int out_size)
{
    const float* nodes     = (const float*)d_in[0];
    const float* edges     = (const float*)d_in[1];
    const int*   senders   = (const int*)d_in[2];
    const int*   receivers = (const int*)d_in[3];
    const float* w_node    = (const float*)d_in[4];
    const float* b_node    = (const float*)d_in[5];
    const float* w_edge    = (const float*)d_in[6];
    const float* b_edge    = (const float*)d_in[7];
    const float* ln_n_s    = (const float*)d_in[8];
    const float* ln_n_o    = (const float*)d_in[9];
    const float* ln_e_s    = (const float*)d_in[10];
    const float* ln_e_o    = (const float*)d_in[11];
    const float* msg_w1    = (const float*)d_in[12];
    const float* msg_b1    = (const float*)d_in[13];
    const float* msg_w2    = (const float*)d_in[14];
    const float* msg_b2    = (const float*)d_in[15];
    const float* upd_w     = (const float*)d_in[16];
    const float* upd_b     = (const float*)d_in[17];
    const float* ln_s      = (const float*)d_in[18];
    const float* ln_o      = (const float*)d_in[19];

    const int N = in_sizes[0] / D;
    const int E = in_sizes[1] / D;

    int dev = 0, nsm = 148;
    cudaGetDevice(&dev);
    cudaDeviceGetAttribute(&nsm, cudaDevAttrMultiProcessorCount, dev);

    float *pn, *pagg;
    __half *pnh, *peh, *pPs, *pPr, *pwnt, *pwet, *pw1t, *pw2t, *pwut;
    cudaGetSymbolAddress((void**)&pn,   g_n);
    cudaGetSymbolAddress((void**)&pagg, g_agg);
    cudaGetSymbolAddress((void**)&pnh,  g_nh);
    cudaGetSymbolAddress((void**)&peh,  g_eh);
    cudaGetSymbolAddress((void**)&pPs,  g_Psh);
    cudaGetSymbolAddress((void**)&pPr,  g_Prh);
    cudaGetSymbolAddress((void**)&pwnt, g_wnt);
    cudaGetSymbolAddress((void**)&pwet, g_wet);
    cudaGetSymbolAddress((void**)&pw1t, g_w1t);
    cudaGetSymbolAddress((void**)&pw2t, g_w2t);
    cudaGetSymbolAddress((void**)&pwut, g_wut);

    const size_t embed_smem = 52224;
    const size_t g1_smem    = 87040;
    const size_t edge_smem  = 231936;
    const size_t upd_smem   = 101376;

    cudaFuncSetAttribute(embed_f16,       cudaFuncAttributeMaxDynamicSharedMemorySize, (int)embed_smem);
    cudaFuncSetAttribute(gemm1_f16,       cudaFuncAttributeMaxDynamicSharedMemorySize, (int)g1_smem);
    cudaFuncSetAttribute(edge_pipe_f16,   cudaFuncAttributeMaxDynamicSharedMemorySize, (int)edge_smem);
    cudaFuncSetAttribute(node_update_f16, cudaFuncAttributeMaxDynamicSharedMemorySize, (int)upd_smem);

    // ---- all weight transposes in one launch ----
    transpose_all<<<dim3(8, 8, 17), 256>>>(w_node, w_edge, msg_w1, msg_w2, upd_w,
                                           pwnt, pwet, pw1t, pw2t, pwut);

    // ---- embeddings ----
    embed_f16<<<(N + 63) / 64, 256, embed_smem>>>(nodes, pwnt, b_node, ln_n_s, ln_n_o, pn, pnh, N);
    embed_f16<<<(E + 63) / 64, 256, embed_smem>>>(edges, pwet, b_edge, ln_e_s, ln_e_o, (float*)nullptr, peh, E);

    // ---- layers ----
    for (int l = 0; l < 3; l++) {
        gemm1_f16<<<(N + 63) / 64, 256, g1_smem>>>(pnh, pw1t + (size_t)(l * 3 + 0) * 32768, pPs, N);
        gemm1_f16<<<(N + 63) / 64, 256, g1_smem>>>(pnh, pw1t + (size_t)(l * 3 + 1) * 32768, pPr, N);
        cudaMemsetAsync(pagg, 0, (size_t)N * D * sizeof(float), 0);
        edge_pipe_f16<<<nsm, 512, edge_smem>>>(
            peh, pPs, pPr,
            pw1t + (size_t)(l * 3 + 2) * 32768, msg_b1 + (size_t)l * 256,
            pw2t + (size_t)l * 32768, msg_b2 + (size_t)l * 128,
            senders, receivers, pagg, E);
        float* nout = (l == 2) ? (float*)d_out : pn;
        __half* nhout = (l == 2) ? (__half*)nullptr : pnh;
        node_update_f16<<<(N + 63) / 64, 256, upd_smem>>>(
            pn, pnh, pagg, pwut + (size_t)l * 32768, upd_b + (size_t)l * 128,
            ln_s + (size_t)l * 128, ln_o + (size_t)l * 128, nout, nhout, N);
    }
}

// round 15
// speedup vs baseline: 1.4797x; 1.0004x over previous
#include <cuda_runtime.h>
#include <cuda_fp16.h>
#include <stdint.h>
#include <math.h>

#define N_NODES 50000
#define N_EDGES 800000
#define D 128
#define H 256

// ---------------- device scratch ----------------
__device__ __align__(16) float  g_n  [(size_t)N_NODES * D];
__device__ __align__(16) __half g_nh [(size_t)N_NODES * D];
__device__ __align__(16) __half g_eh [(size_t)N_EDGES * D];
__device__ __align__(16) __half g_Psh[(size_t)N_NODES * H];
__device__ __align__(16) __half g_Prh[(size_t)N_NODES * H];
__device__ __align__(16) float  g_agg[(size_t)N_NODES * D];
// pre-transposed fp16 weights ([N][K] K-major)
__device__ __align__(16) __half g_wnt[128 * 128];
__device__ __align__(16) __half g_wet[128 * 128];
__device__ __align__(16) __half g_w1t[9 * 256 * 128];
__device__ __align__(16) __half g_w2t[3 * 128 * 256];
__device__ __align__(16) __half g_wut[3 * 128 * 256];

__device__ __forceinline__ uint32_t s2u(const void* p) {
    uint32_t a;
    asm("{ .reg .u64 t; cvta.to.shared.u64 t, %1; cvt.u32.u64 %0, t; }" : "=r"(a) : "l"(p));
    return a;
}
__device__ __forceinline__ void ldsm4(uint32_t* r, uint32_t a) {
    asm volatile("ldmatrix.sync.aligned.m8n8.x4.shared.b16 {%0,%1,%2,%3}, [%4];"
        : "=r"(r[0]), "=r"(r[1]), "=r"(r[2]), "=r"(r[3]) : "r"(a));
}
__device__ __forceinline__ void mma16816(float* c, const uint32_t* a, uint32_t b0, uint32_t b1) {
    asm volatile("mma.sync.aligned.m16n8k16.row.col.f32.f16.f16.f32 "
        "{%0,%1,%2,%3},{%4,%5,%6,%7},{%8,%9},{%0,%1,%2,%3};"
        : "+f"(c[0]), "+f"(c[1]), "+f"(c[2]), "+f"(c[3])
        : "r"(a[0]), "r"(a[1]), "r"(a[2]), "r"(a[3]), "r"(b0), "r"(b1));
}
__device__ __forceinline__ void cpa16(uint32_t smem, const void* g) {
    asm volatile("cp.async.cg.shared.global [%0], [%1], 16;" :: "r"(smem), "l"(g) : "memory");
}
#define CP_COMMIT() asm volatile("cp.async.commit_group;" ::: "memory")
#define CP_WAIT(n)  asm volatile("cp.async.wait_group %0;" :: "n"(n) : "memory")

// fast gelu: tanh via ex2.approx-based __expf (rel err ~1e-6, ~6 instr)
__device__ __forceinline__ float gelu_tanh(float x) {
    const float c = 0.7978845608028654f;
    float y = c * (x + 0.044715f * x * x * x);
    float u = fminf(fmaxf(2.f * y, -30.f), 30.f);
    float e = __expf(u);
    float t = __fdividef(e - 1.f, e + 1.f);
    return 0.5f * x * (1.0f + t);
}

// ------------- padded-row GEMM core (SA = K*2+16), 32-row warp tiles -------------
template<int K, int NTW>
__device__ __forceinline__ void mma_loop(uint32_t abase, uint32_t bbase,
                                         float (&acc)[2][NTW][4], int wm, int wn, int lane)
{
    const int SA = K * 2 + 16;
    int mat  = lane >> 3;
    int arow = (lane & 7) + ((mat & 1) << 3);
    int akb  = (mat >> 1) << 4;
    int brow = (lane & 7) + ((mat >> 1) << 3);
    int bkb  = (mat & 1) << 4;
    uint32_t a0 = abase + (wm * 32 + arow) * SA + akb;
    uint32_t b0 = bbase + (wn * (8 * NTW) + brow) * SA + bkb;
#pragma unroll
    for (int kt = 0; kt < K / 16; kt++) {
        uint32_t A[2][4], B[NTW / 2][4];
        ldsm4(A[0], a0 + kt * 32);
        ldsm4(A[1], a0 + 16 * SA + kt * 32);
#pragma unroll
        for (int j = 0; j < NTW / 2; j++)
            ldsm4(B[j], b0 + j * 16 * SA + kt * 32);
#pragma unroll
        for (int i = 0; i < 2; i++)
#pragma unroll
            for (int j = 0; j < NTW / 2; j++) {
                mma16816(acc[i][2 * j],     A[i], B[j][0], B[j][1]);
                mma16816(acc[i][2 * j + 1], A[i], B[j][2], B[j][3]);
            }
    }
}

// ------------- 16-row warp tile core: A and B both XOR-swizzled -------------
template<int K, int NTW, int SA, int SB>
__device__ __forceinline__ void mma_loop_16sw(uint32_t abase, uint32_t bbase,
                                              float (&acc)[NTW][4], int wm, int wn, int lane)
{
    int mat  = lane >> 3;
    int arow = (lane & 7) + ((mat & 1) << 3);
    int akb  = (mat >> 1) << 4;
    int brow = (lane & 7) + ((mat >> 1) << 3);
    int bkb  = (mat & 1) << 4;
    uint32_t ar = wm * 16 + arow;
    uint32_t sw_a = (ar & 7) << 4;
#pragma unroll
    for (int kt = 0; kt < K / 16; kt++) {
        uint32_t A[4], B[NTW / 2][4];
        uint32_t ak = (uint32_t)(akb + kt * 32);
        ldsm4(A, abase + ar * SA + (ak ^ sw_a));
#pragma unroll
        for (int j = 0; j < NTW / 2; j++) {
            uint32_t br = wn * (8 * NTW) + brow + j * 16;
            uint32_t bk = (uint32_t)(bkb + kt * 32);
            ldsm4(B[j], bbase + br * SB + (bk ^ ((br & 7) << 4)));
        }
#pragma unroll
        for (int j = 0; j < NTW / 2; j++) {
            mma16816(acc[2 * j],     A, B[j][0], B[j][1]);
            mma16816(acc[2 * j + 1], A, B[j][2], B[j][3]);
        }
    }
}

// =====================================================================================
// transpose_all
// =====================================================================================
__global__ void transpose_all(const float* __restrict__ w_node, const float* __restrict__ w_edge,
                              const float* __restrict__ msg_w1, const float* __restrict__ msg_w2,
                              const float* __restrict__ upd_w,
                              __half* __restrict__ wnt, __half* __restrict__ wet,
                              __half* __restrict__ w1t, __half* __restrict__ w2t,
                              __half* __restrict__ wut)
{
    int z = blockIdx.z;
    const float* src; __half* dst; int K, N;
    if (z == 0)      { src = w_node; dst = wnt; K = 128; N = 128; }
    else if (z == 1) { src = w_edge; dst = wet; K = 128; N = 128; }
    else if (z < 11) {
        int j = z - 2, l = j / 3, p = j % 3;
        src = msg_w1 + (size_t)l * 384 * 256 + (size_t)p * 128 * 256;
        dst = w1t + (size_t)j * 32768; K = 128; N = 256;
    } else if (z < 14) {
        int l = z - 11;
        src = msg_w2 + (size_t)l * 256 * 128; dst = w2t + (size_t)l * 32768; K = 256; N = 128;
    } else {
        int l = z - 14;
        src = upd_w + (size_t)l * 256 * 128; dst = wut + (size_t)l * 32768; K = 256; N = 128;
    }
    int k0 = blockIdx.x * 32, n0 = blockIdx.y * 32;
    if (k0 >= K || n0 >= N) return;
    __shared__ float t[32][33];
    int tx = threadIdx.x & 31, ty = threadIdx.x >> 5;
    for (int i = ty; i < 32; i += 8) {
        int k = k0 + i, n = n0 + tx;
        t[i][tx] = (k < K && n < N) ? src[(size_t)k * N + n] : 0.f;
    }
    __syncthreads();
    for (int i = ty; i < 32; i += 8) {
        int n = n0 + i, k = k0 + tx;
        if (n < N && k < K) dst[(size_t)n * K + k] = __float2half(t[tx][i]);
    }
}

// =====================================================================================
// embed: out = LN(gelu(x@W + b)). K=128, N=128. 64 rows/CTA, 256 thr, 2 CTAs/SM.
// smem: A 17408 + W 34816 = 52224 (Csm 64x132 f32 = 33792 overlays)
// =====================================================================================
__global__ __launch_bounds__(256, 2)
void embed_f16(const float* __restrict__ x, const __half* __restrict__ Wt,
               const float* __restrict__ bias,
               const float* __restrict__ lns, const float* __restrict__ lno,
               float* __restrict__ outf, __half* __restrict__ outh, int M)
{
    extern __shared__ char sm[];
    char* Asm = sm;                 // 64 x 272
    char* Bsm = sm + 17408;         // 128 x 272
    const int tid = threadIdx.x, w = tid >> 5, lane = tid & 31;
    const int wm = w >> 2, wn = w & 3;
    const size_t row0 = (size_t)blockIdx.x * 64;

    for (int i = tid; i < 64 * 16; i += 256) {
        int r = i >> 4, c = i & 15;
        uint32_t o[4] = {0, 0, 0, 0};
        if (row0 + r < (size_t)M) {
            const float* src = x + (row0 + r) * 128 + c * 8;
            float4 a = ((const float4*)src)[0], b = ((const float4*)src)[1];
            __half2 h0 = __floats2half2_rn(a.x, a.y), h1 = __floats2half2_rn(a.z, a.w);
            __half2 h2 = __floats2half2_rn(b.x, b.y), h3 = __floats2half2_rn(b.z, b.w);
            o[0] = *(uint32_t*)&h0; o[1] = *(uint32_t*)&h1; o[2] = *(uint32_t*)&h2; o[3] = *(uint32_t*)&h3;
        }
        *(uint4*)(Asm + r * 272 + c * 16) = *(uint4*)o;
    }
    for (int i = tid; i < 128 * 16; i += 256) {
        int r = i >> 4, c = i & 15;
        *(uint4*)(Bsm + r * 272 + c * 16) = *(const uint4*)(Wt + r * 128 + c * 8);
    }
    __syncthreads();

    float acc[2][4][4] = {};
    mma_loop<128, 4>(s2u(Asm), s2u(Bsm), acc, wm, wn, lane);
    __syncthreads();

    float* Csm = (float*)sm;   // 64 x 132
    const int gid = lane >> 2, tig = lane & 3;
    const int rb = wm * 32 + gid, cb = wn * 32 + tig * 2;
#pragma unroll
    for (int i = 0; i < 2; i++)
#pragma unroll
        for (int nt = 0; nt < 4; nt++) {
            int col = cb + nt * 8;
            int r = rb + i * 16;
            Csm[r * 132 + col]           = gelu_tanh(acc[i][nt][0] + bias[col]);
            Csm[r * 132 + col + 1]       = gelu_tanh(acc[i][nt][1] + bias[col + 1]);
            Csm[(r + 8) * 132 + col]     = gelu_tanh(acc[i][nt][2] + bias[col]);
            Csm[(r + 8) * 132 + col + 1] = gelu_tanh(acc[i][nt][3] + bias[col + 1]);
        }
    __syncthreads();

    int r = tid >> 2, s = tid & 3;   // r in [0,64)
    float4 v[8];
    float sum = 0.f;
#pragma unroll
    for (int k = 0; k < 8; k++) {
        v[k] = *(float4*)&Csm[r * 132 + s * 4 + k * 16];
        sum += v[k].x + v[k].y + v[k].z + v[k].w;
    }
    sum += __shfl_xor_sync(0xffffffffu, sum, 1);
    sum += __shfl_xor_sync(0xffffffffu, sum, 2);
    float mean = sum * (1.0f / 128.0f);
    float q = 0.f;
#pragma unroll
    for (int k = 0; k < 8; k++) {
        float dx = v[k].x - mean, dy = v[k].y - mean, dz = v[k].z - mean, dw = v[k].w - mean;
        q += dx * dx + dy * dy + dz * dz + dw * dw;
    }
    q += __shfl_xor_sync(0xffffffffu, q, 1);
    q += __shfl_xor_sync(0xffffffffu, q, 2);
    float rstd = rsqrtf(q * (1.0f / 128.0f) + 1e-5f);

    size_t row = row0 + r;
    if (row < (size_t)M) {
#pragma unroll
        for (int k = 0; k < 8; k++) {
            int col = s * 4 + k * 16;
            float4 sc = *(const float4*)(lns + col), of = *(const float4*)(lno + col);
            float4 o;
            o.x = (v[k].x - mean) * rstd * sc.x + of.x;
            o.y = (v[k].y - mean) * rstd * sc.y + of.y;
            o.z = (v[k].z - mean) * rstd * sc.z + of.z;
            o.w = (v[k].w - mean) * rstd * sc.w + of.w;
            if (outf) *(float4*)(outf + row * 128 + col) = o;
            if (outh) {
                __half2 h0 = __floats2half2_rn(o.x, o.y), h1 = __floats2half2_rn(o.z, o.w);
                ((uint32_t*)(outh + row * 128 + col))[0] = *(uint32_t*)&h0;
                ((uint32_t*)(outh + row * 128 + col))[1] = *(uint32_t*)&h1;
            }
        }
    }
}

// =====================================================================================
// gemm1: C[M,256] = A[M,128] @ Bt[256][128]. 64 rows/CTA, 256 thr, 2 CTAs/SM.
// smem: A 17408 + B 69632 = 87040
// =====================================================================================
__global__ __launch_bounds__(256, 2)
void gemm1_f16(const __half* __restrict__ A, const __half* __restrict__ Bt,
               __half* __restrict__ C, int M)
{
    extern __shared__ char sm[];
    char* Asm = sm;                 // 64 x 272
    char* Bsm = sm + 17408;         // 256 x 272
    const int tid = threadIdx.x, w = tid >> 5, lane = tid & 31;
    const int wm = w >> 2, wn = w & 3;
    const size_t row0 = (size_t)blockIdx.x * 64;

    for (int i = tid; i < 64 * 16; i += 256) {
        int r = i >> 4, c = i & 15;
        uint4 v = make_uint4(0, 0, 0, 0);
        if (row0 + r < (size_t)M) v = *(const uint4*)(A + (row0 + r) * 128 + c * 8);
        *(uint4*)(Asm + r * 272 + c * 16) = v;
    }
    for (int i = tid; i < 256 * 16; i += 256) {
        int r = i >> 4, c = i & 15;
        *(uint4*)(Bsm + r * 272 + c * 16) = *(const uint4*)(Bt + (size_t)r * 128 + c * 8);
    }
    __syncthreads();

    float acc[2][8][4] = {};
    mma_loop<128, 8>(s2u(Asm), s2u(Bsm), acc, wm, wn, lane);

    const int gid = lane >> 2, tig = lane & 3;
    const int rb = wm * 32 + gid, cb = wn * 64 + tig * 2;
#pragma unroll
    for (int i = 0; i < 2; i++) {
        size_t r = row0 + rb + i * 16;
#pragma unroll
        for (int nt = 0; nt < 8; nt++) {
            int col = cb + nt * 8;
            __half2 h01 = __floats2half2_rn(acc[i][nt][0], acc[i][nt][1]);
            __half2 h23 = __floats2half2_rn(acc[i][nt][2], acc[i][nt][3]);
            if (r < (size_t)M)     *(__half2*)(C + r * 256 + col) = h01;
            if (r + 8 < (size_t)M) *(__half2*)(C + (r + 8) * 256 + col) = h23;
        }
    }
}

// =====================================================================================
// edge_pipe: persistent, 64-edge tiles, 2-deep cp.async pipeline. (unchanged from R11)
// =====================================================================================
__global__ __launch_bounds__(512, 1)
void edge_pipe_f16(const __half* __restrict__ eh,
                   const __half* __restrict__ Ps, const __half* __restrict__ Pr,
                   const __half* __restrict__ W1ct, const float* __restrict__ b1,
                   const __half* __restrict__ W2t,  const float* __restrict__ b2,
                   const int* __restrict__ snd, const int* __restrict__ rcv,
                   float* __restrict__ agg, int E)
{
    extern __shared__ char sm[];
    int*   sidx = (int*)sm;              // [2][64]
    int*   ridx = (int*)(sm + 512);      // [2][64]
    float* b1s  = (float*)(sm + 1024);   // 256
    float* b2s  = (float*)(sm + 2048);   // 128
    char* B1 = sm + 2560;                // 65536
    char* B2 = sm + 68096;               // 65536
    char* AE = sm + 133632;              // 2 x 16384
    char* PSb = sm + 166400;             // 32768 (becomes m1)
    char* PRb = sm + 199168;             // 32768
    const int tid = threadIdx.x, w = tid >> 5, lane = tid & 31;
    const int wm = w >> 2, wn = w & 3;
    const int gid = lane >> 2, tig = lane & 3;
    const uint32_t sidx_u = s2u(sidx), ridx_u = s2u(ridx);
    const uint32_t ae_u = s2u(AE), ps_u = s2u(PSb), pr_u = s2u(PRb);
    const uint32_t b1_u = s2u(B1), b2_u = s2u(B2);

    for (int i = tid; i < 256 * 16; i += 512) {
        int r = i >> 4, c = i & 15;
        *(uint4*)(B1 + r * 256 + (((uint32_t)c * 16) ^ ((r & 7) << 4))) =
            *(const uint4*)(W1ct + (size_t)r * 128 + c * 8);
    }
    for (int i = tid; i < 128 * 32; i += 512) {
        int r = i >> 5, c = i & 31;
        *(uint4*)(B2 + r * 512 + (((uint32_t)c * 16) ^ ((r & 7) << 4))) =
            *(const uint4*)(W2t + (size_t)r * 256 + c * 8);
    }
    if (tid < 256) b1s[tid] = b1[tid];
    if (tid >= 256 && tid < 384) b2s[tid - 256] = b2[tid - 256];
    __syncthreads();

    const int nblk = (E + 63) >> 6;
    const int bx = blockIdx.x, gsz = gridDim.x;
    const int T = (nblk > bx) ? ((nblk - bx + gsz - 1) / gsz) : 0;
    if (T <= 0) return;

    const int idx_clamp = ((E - 4) > 0) ? ((E - 4) & ~3) : 0;

    auto issue_idxA = [&](int u) {
        int e0n = (bx + u * gsz) << 6;
        int slot = u & 1;
        if (tid < 16) {
            int off = e0n + tid * 4; if (off > idx_clamp) off = idx_clamp;
            cpa16(sidx_u + slot * 256 + tid * 16, snd + off);
        } else if (tid < 32) {
            int t2 = tid - 16;
            int off = e0n + t2 * 4; if (off > idx_clamp) off = idx_clamp;
            cpa16(ridx_u + slot * 256 + t2 * 16, rcv + off);
        }
        for (int i = tid; i < 1024; i += 512) {
            int r = i >> 4, c = i & 15;
            int eg = e0n + r; if (eg > E - 1) eg = E - 1;
            cpa16(ae_u + slot * 16384 + r * 256 + (((uint32_t)c * 16) ^ ((r & 7) << 4)),
                  eh + (size_t)eg * 128 + c * 8);
        }
    };

    issue_idxA(0);
    CP_COMMIT();

    for (int u = 0; u < T; u++) {
        const int slot = u & 1;
        const int e0 = (bx + u * gsz) << 6;

        CP_WAIT(0);
        __syncthreads();

        const int r0 = wm * 16 + gid, r1 = r0 + 8;
        const int rv0 = (e0 + r0 < E) ? ridx[slot * 64 + r0] : -1;
        const int rv1 = (e0 + r1 < E) ? ridx[slot * 64 + r1] : -1;

        for (int i = tid; i < 2048; i += 512) {
            int r = i >> 5, c = i & 31;
            int sv = sidx[slot * 64 + r];
            cpa16(ps_u + r * 512 + (((uint32_t)c * 16) ^ ((r & 7) << 4)),
                  Ps + (size_t)sv * 256 + c * 8);
        }
        for (int i = tid; i < 2048; i += 512) {
            int r = i >> 5, c = i & 31;
            int rv = ridx[slot * 64 + r];
            cpa16(pr_u + r * 512 + (((uint32_t)c * 16) ^ ((r & 7) << 4)),
                  Pr + (size_t)rv * 256 + c * 8);
        }
        CP_COMMIT();

        if (u + 1 < T) issue_idxA(u + 1);
        CP_COMMIT();

        float acc1[8][4] = {};
        mma_loop_16sw<128, 8, 256, 256>(ae_u + slot * 16384, b1_u, acc1, wm, wn, lane);

        CP_WAIT(1);
        __syncthreads();

#pragma unroll
        for (int nt = 0; nt < 8; nt++) {
            int c = wn * 64 + nt * 8 + tig * 2;
            float bxv = b1s[c], byv = b1s[c + 1];
#pragma unroll
            for (int hh = 0; hh < 2; hh++) {
                int r = wm * 16 + gid + hh * 8;
                uint32_t off = r * 512 + (((uint32_t)(c * 2)) ^ ((r & 7) << 4));
                float2 fa = __half22float2(*(__half2*)(PSb + off));
                float2 fb = __half22float2(*(__half2*)(PRb + off));
                float xx = fmaxf(acc1[nt][2 * hh]     + fa.x + fb.x + bxv, 0.f);
                float yy = fmaxf(acc1[nt][2 * hh + 1] + fa.y + fb.y + byv, 0.f);
                *(__half2*)(PSb + off) = __floats2half2_rn(xx, yy);
            }
        }
        __syncthreads();

        float acc2[4][4] = {};
        mma_loop_16sw<256, 4, 512, 512>(ps_u, b2_u, acc2, wm, wn, lane);

#pragma unroll
        for (int nt = 0; nt < 4; nt++) {
            int c = wn * 32 + nt * 8 + tig * 2;
            float2 bb = *(float2*)&b2s[c];
            if (rv0 >= 0) {
                float2 v0 = make_float2(fmaxf(acc2[nt][0] + bb.x, 0.f),
                                        fmaxf(acc2[nt][1] + bb.y, 0.f));
                atomicAdd((float2*)(agg + (size_t)rv0 * 128 + c), v0);
            }
            if (rv1 >= 0) {
                float2 v1 = make_float2(fmaxf(acc2[nt][2] + bb.x, 0.f),
                                        fmaxf(acc2[nt][3] + bb.y, 0.f));
                atomicAdd((float2*)(agg + (size_t)rv1 * 128 + c), v1);
            }
        }
    }
}

// =====================================================================================
// node_update: upd = LN(concat(nh, agg) @ Wu + b); out = n + upd.
// K=256, N=128. 64 rows/CTA, 256 thr, 2 CTAs/SM. smem: A 33792 + B 67584 = 101376
// =====================================================================================
__global__ __launch_bounds__(256, 2)
void node_update_f16(const float* __restrict__ nf, const __half* __restrict__ nh,
                     const float* __restrict__ agg, const __half* __restrict__ Wut,
                     const float* __restrict__ bias,
                     const float* __restrict__ lns, const float* __restrict__ lno,
                     float* __restrict__ outf, __half* __restrict__ outh, int M)
{
    extern __shared__ char sm[];
    char* Asm = sm;                 // 64 x 528
    char* Bsm = sm + 33792;         // 128 x 528
    const int tid = threadIdx.x, w = tid >> 5, lane = tid & 31;
    const int wm = w >> 2, wn = w & 3;
    const size_t row0 = (size_t)blockIdx.x * 64;

    for (int i = tid; i < 64 * 32; i += 256) {
        int r = i >> 5, c = i & 31, k0 = c * 8;
        uint32_t o[4] = {0, 0, 0, 0};
        size_t row = row0 + r;
        if (row < (size_t)M) {
            if (k0 < 128) {
                *(uint4*)o = *(const uint4*)(nh + row * 128 + k0);
            } else {
                const float* src = agg + row * 128 + (k0 - 128);
                float4 a = ((const float4*)src)[0], b = ((const float4*)src)[1];
                __half2 h0 = __floats2half2_rn(a.x, a.y), h1 = __floats2half2_rn(a.z, a.w);
                __half2 h2 = __floats2half2_rn(b.x, b.y), h3 = __floats2half2_rn(b.z, b.w);
                o[0] = *(uint32_t*)&h0; o[1] = *(uint32_t*)&h1; o[2] = *(uint32_t*)&h2; o[3] = *(uint32_t*)&h3;
            }
        }
        *(uint4*)(Asm + r * 528 + c * 16) = *(uint4*)o;
    }
    for (int i = tid; i < 128 * 32; i += 256) {
        int r = i >> 5, c = i & 31;
        *(uint4*)(Bsm + r * 528 + c * 16) = *(const uint4*)(Wut + (size_t)r * 256 + c * 8);
    }
    __syncthreads();

    float acc[2][4][4] = {};
    mma_loop<256, 4>(s2u(Asm), s2u(Bsm), acc, wm, wn, lane);
    __syncthreads();

    float* Csm = (float*)Asm;   // 64 x 132
    const int gid = lane >> 2, tig = lane & 3;
    const int rb = wm * 32 + gid, cb = wn * 32 + tig * 2;
#pragma unroll
    for (int i = 0; i < 2; i++)
#pragma unroll
        for (int nt = 0; nt < 4; nt++) {
            int col = cb + nt * 8;
            int r = rb + i * 16;
            Csm[r * 132 + col]           = acc[i][nt][0] + bias[col];
            Csm[r * 132 + col + 1]       = acc[i][nt][1] + bias[col + 1];
            Csm[(r + 8) * 132 + col]     = acc[i][nt][2] + bias[col];
            Csm[(r + 8) * 132 + col + 1] = acc[i][nt][3] + bias[col + 1];
        }
    __syncthreads();

    int r = tid >> 2, s = tid & 3;   // r in [0,64)
    float4 v[8];
    float sum = 0.f;
#pragma unroll
    for (int k = 0; k < 8; k++) {
        v[k] = *(float4*)&Csm[r * 132 + s * 4 + k * 16];
        sum += v[k].x + v[k].y + v[k].z + v[k].w;
    }
    sum += __shfl_xor_sync(0xffffffffu, sum, 1);
    sum += __shfl_xor_sync(0xffffffffu, sum, 2);
    float mean = sum * (1.0f / 128.0f);
    float q = 0.f;
#pragma unroll
    for (int k = 0; k < 8; k++) {
        float dx = v[k].x - mean, dy = v[k].y - mean, dz = v[k].z - mean, dw = v[k].w - mean;
        q += dx * dx + dy * dy + dz * dz + dw * dw;
    }
    q += __shfl_xor_sync(0xffffffffu, q, 1);
    q += __shfl_xor_sync(0xffffffffu, q, 2);
    float rstd = rsqrtf(q * (1.0f / 128.0f) + 1e-5f);

    size_t row = row0 + r;
    if (row < (size_t)M) {
#pragma unroll
        for (int k = 0; k < 8; k++) {
            int col = s * 4 + k * 16;
            float4 sc = *(const float4*)(lns + col), of = *(const float4*)(lno + col);
            float4 res = *(const float4*)(nf + row * 128 + col);
            float4 o;
            o.x = res.x + (v[k].x - mean) * rstd * sc.x + of.x;
            o.y = res.y + (v[k].y - mean) * rstd * sc.y + of.y;
            o.z = res.z + (v[k].z - mean) * rstd * sc.z + of.z;
            o.w = res.w + (v[k].w - mean) * rstd * sc.w + of.w;
            if (outf) *(float4*)(outf + row * 128 + col) = o;
            if (outh) {
                __half2 h0 = __floats2half2_rn(o.x, o.y), h1 = __floats2half2_rn(o.z, o.w);
                ((uint32_t*)(outh + row * 128 + col))[0] = *(uint32_t*)&h0;
                ((uint32_t*)(outh + row * 128 + col))[1] = *(uint32_t*)&h1;
            }
        }
    }
}

// =====================================================================================
extern "C" void kernel_launch(void* const* d_in, const int* in_sizes, int n_in,
                              void* d_out, int out_size)
{
    const float* nodes     = (const float*)d_in[0];
    const float* edges     = (const float*)d_in[1];
    const int*   senders   = (const int*)d_in[2];
    const int*   receivers = (const int*)d_in[3];
    const float* w_node    = (const float*)d_in[4];
    const float* b_node    = (const float*)d_in[5];
    const float* w_edge    = (const float*)d_in[6];
    const float* b_edge    = (const float*)d_in[7];
    const float* ln_n_s    = (const float*)d_in[8];
    const float* ln_n_o    = (const float*)d_in[9];
    const float* ln_e_s    = (const float*)d_in[10];
    const float* ln_e_o    = (const float*)d_in[11];
    const float* msg_w1    = (const float*)d_in[12];
    const float* msg_b1    = (const float*)d_in[13];
    const float* msg_w2    = (const float*)d_in[14];
    const float* msg_b2    = (const float*)d_in[15];
    const float* upd_w     = (const float*)d_in[16];
    const float* upd_b     = (const float*)d_in[17];
    const float* ln_s      = (const float*)d_in[18];
    const float* ln_o      = (const float*)d_in[19];

    const int N = in_sizes[0] / D;
    const int E = in_sizes[1] / D;

    int dev = 0, nsm = 148;
    cudaGetDevice(&dev);
    cudaDeviceGetAttribute(&nsm, cudaDevAttrMultiProcessorCount, dev);

    float *pn, *pagg;
    __half *pnh, *peh, *pPs, *pPr, *pwnt, *pwet, *pw1t, *pw2t, *pwut;
    cudaGetSymbolAddress((void**)&pn,   g_n);
    cudaGetSymbolAddress((void**)&pagg, g_agg);
    cudaGetSymbolAddress((void**)&pnh,  g_nh);
    cudaGetSymbolAddress((void**)&peh,  g_eh);
    cudaGetSymbolAddress((void**)&pPs,  g_Psh);
    cudaGetSymbolAddress((void**)&pPr,  g_Prh);
    cudaGetSymbolAddress((void**)&pwnt, g_wnt);
    cudaGetSymbolAddress((void**)&pwet, g_wet);
    cudaGetSymbolAddress((void**)&pw1t, g_w1t);
    cudaGetSymbolAddress((void**)&pw2t, g_w2t);
    cudaGetSymbolAddress((void**)&pwut, g_wut);

    const size_t embed_smem = 52224;
    const size_t g1_smem    = 87040;
    const size_t edge_smem  = 231936;
    const size_t upd_smem   = 101376;

    cudaFuncSetAttribute(embed_f16,       cudaFuncAttributeMaxDynamicSharedMemorySize, (int)embed_smem);
    cudaFuncSetAttribute(gemm1_f16,       cudaFuncAttributeMaxDynamicSharedMemorySize, (int)g1_smem);
    cudaFuncSetAttribute(edge_pipe_f16,   cudaFuncAttributeMaxDynamicSharedMemorySize, (int)edge_smem);
    cudaFuncSetAttribute(node_update_f16, cudaFuncAttributeMaxDynamicSharedMemorySize, (int)upd_smem);

    // ---- all weight transposes in one launch ----
    transpose_all<<<dim3(8, 8, 17), 256>>>(w_node, w_edge, msg_w1, msg_w2, upd_w,
                                           pwnt, pwet, pw1t, pw2t, pwut);

    // ---- embeddings ----
    embed_f16<<<(N + 63) / 64, 256, embed_smem>>>(nodes, pwnt, b_node, ln_n_s, ln_n_o, pn, pnh, N);
    embed_f16<<<(E + 63) / 64, 256, embed_smem>>>(edges, pwet, b_edge, ln_e_s, ln_e_o, (float*)nullptr, peh, E);

    // ---- layers ----
    for (int l = 0; l < 3; l++) {
        gemm1_f16<<<(N + 63) / 64, 256, g1_smem>>>(pnh, pw1t + (size_t)(l * 3 + 0) * 32768, pPs, N);
        gemm1_f16<<<(N + 63) / 64, 256, g1_smem>>>(pnh, pw1t + (size_t)(l * 3 + 1) * 32768, pPr, N);
        cudaMemsetAsync(pagg, 0, (size_t)N * D * sizeof(float), 0);
        edge_pipe_f16<<<nsm, 512, edge_smem>>>(
            peh, pPs, pPr,
            pw1t + (size_t)(l * 3 + 2) * 32768, msg_b1 + (size_t)l * 256,
            pw2t + (size_t)l * 32768, msg_b2 + (size_t)l * 128,
            senders, receivers, pagg, E);
        float* nout = (l == 2) ? (float*)d_out : pn;
        __half* nhout = (l == 2) ? (__half*)nullptr : pnh;
        node_update_f16<<<(N + 63) / 64, 256, upd_smem>>>(
            pn, pnh, pagg, pwut + (size_t)l * 32768, upd_b + (size_t)l * 128,
            ln_s + (size_t)l * 128, ln_o + (size_t)l * 128, nout, nhout, N);
    }
}

// round 17
// speedup vs baseline: 1.4982x; 1.0125x over previous
#include <cuda_runtime.h>
#include <cuda_fp16.h>
#include <stdint.h>
#include <math.h>

#define N_NODES 50000
#define N_EDGES 800000
#define D 128
#define H 256

// ---------------- device scratch ----------------
__device__ __align__(16) float  g_n  [(size_t)N_NODES * D];
__device__ __align__(16) __half g_nh [(size_t)N_NODES * D];
__device__ __align__(16) __half g_eh [(size_t)N_EDGES * D];
__device__ __align__(16) __half g_Psh[(size_t)N_NODES * H];
__device__ __align__(16) __half g_Prh[(size_t)N_NODES * H];
__device__ __align__(16) float  g_agg[(size_t)N_NODES * D];
// pre-transposed fp16 weights ([N][K] K-major)
__device__ __align__(16) __half g_wnt[128 * 128];
__device__ __align__(16) __half g_wet[128 * 128];
__device__ __align__(16) __half g_w1t[9 * 256 * 128];
__device__ __align__(16) __half g_w2t[3 * 128 * 256];
__device__ __align__(16) __half g_wut[3 * 128 * 256];

__device__ __forceinline__ uint32_t s2u(const void* p) {
    uint32_t a;
    asm("{ .reg .u64 t; cvta.to.shared.u64 t, %1; cvt.u32.u64 %0, t; }" : "=r"(a) : "l"(p));
    return a;
}
__device__ __forceinline__ void ldsm4(uint32_t* r, uint32_t a) {
    asm volatile("ldmatrix.sync.aligned.m8n8.x4.shared.b16 {%0,%1,%2,%3}, [%4];"
        : "=r"(r[0]), "=r"(r[1]), "=r"(r[2]), "=r"(r[3]) : "r"(a));
}
__device__ __forceinline__ void mma16816(float* c, const uint32_t* a, uint32_t b0, uint32_t b1) {
    asm volatile("mma.sync.aligned.m16n8k16.row.col.f32.f16.f16.f32 "
        "{%0,%1,%2,%3},{%4,%5,%6,%7},{%8,%9},{%0,%1,%2,%3};"
        : "+f"(c[0]), "+f"(c[1]), "+f"(c[2]), "+f"(c[3])
        : "r"(a[0]), "r"(a[1]), "r"(a[2]), "r"(a[3]), "r"(b0), "r"(b1));
}
__device__ __forceinline__ void cpa16(uint32_t smem, const void* g) {
    asm volatile("cp.async.cg.shared.global [%0], [%1], 16;" :: "r"(smem), "l"(g) : "memory");
}
#define CP_COMMIT() asm volatile("cp.async.commit_group;" ::: "memory")
#define CP_WAIT(n)  asm volatile("cp.async.wait_group %0;" :: "n"(n) : "memory")
__device__ __forceinline__ void barg(int id) {
    asm volatile("bar.sync %0, 256;" :: "r"(id) : "memory");
}

// fast gelu: tanh via ex2.approx-based __expf (rel err ~1e-6)
__device__ __forceinline__ float gelu_tanh(float x) {
    const float c = 0.7978845608028654f;
    float y = c * (x + 0.044715f * x * x * x);
    float u = fminf(fmaxf(2.f * y, -30.f), 30.f);
    float e = __expf(u);
    float t = __fdividef(e - 1.f, e + 1.f);
    return 0.5f * x * (1.0f + t);
}

// ------------- padded-row GEMM core (SA = K*2+16), 32-row warp tiles -------------
template<int K, int NTW>
__device__ __forceinline__ void mma_loop(uint32_t abase, uint32_t bbase,
                                         float (&acc)[2][NTW][4], int wm, int wn, int lane)
{
    const int SA = K * 2 + 16;
    int mat  = lane >> 3;
    int arow = (lane & 7) + ((mat & 1) << 3);
    int akb  = (mat >> 1) << 4;
    int brow = (lane & 7) + ((mat >> 1) << 3);
    int bkb  = (mat & 1) << 4;
    uint32_t a0 = abase + (wm * 32 + arow) * SA + akb;
    uint32_t b0 = bbase + (wn * (8 * NTW) + brow) * SA + bkb;
#pragma unroll
    for (int kt = 0; kt < K / 16; kt++) {
        uint32_t A[2][4], B[NTW / 2][4];
        ldsm4(A[0], a0 + kt * 32);
        ldsm4(A[1], a0 + 16 * SA + kt * 32);
#pragma unroll
        for (int j = 0; j < NTW / 2; j++)
            ldsm4(B[j], b0 + j * 16 * SA + kt * 32);
#pragma unroll
        for (int i = 0; i < 2; i++)
#pragma unroll
            for (int j = 0; j < NTW / 2; j++) {
                mma16816(acc[i][2 * j],     A[i], B[j][0], B[j][1]);
                mma16816(acc[i][2 * j + 1], A[i], B[j][2], B[j][3]);
            }
    }
}

// ------------- 16-row warp tile core: A and B both XOR-swizzled -------------
template<int K, int NTW, int SA, int SB>
__device__ __forceinline__ void mma_loop_16sw(uint32_t abase, uint32_t bbase,
                                              float (&acc)[NTW][4], int wm, int wn, int lane)
{
    int mat  = lane >> 3;
    int arow = (lane & 7) + ((mat & 1) << 3);
    int akb  = (mat >> 1) << 4;
    int brow = (lane & 7) + ((mat >> 1) << 3);
    int bkb  = (mat & 1) << 4;
    uint32_t ar = wm * 16 + arow;
    uint32_t sw_a = (ar & 7) << 4;
#pragma unroll
    for (int kt = 0; kt < K / 16; kt++) {
        uint32_t A[4], B[NTW / 2][4];
        uint32_t ak = (uint32_t)(akb + kt * 32);
        ldsm4(A, abase + ar * SA + (ak ^ sw_a));
#pragma unroll
        for (int j = 0; j < NTW / 2; j++) {
            uint32_t br = wn * (8 * NTW) + brow + j * 16;
            uint32_t bk = (uint32_t)(bkb + kt * 32);
            ldsm4(B[j], bbase + br * SB + (bk ^ ((br & 7) << 4)));
        }
#pragma unroll
        for (int j = 0; j < NTW / 2; j++) {
            mma16816(acc[2 * j],     A, B[j][0], B[j][1]);
            mma16816(acc[2 * j + 1], A, B[j][2], B[j][3]);
        }
    }
}

// =====================================================================================
// transpose_all
// =====================================================================================
__global__ void transpose_all(const float* __restrict__ w_node, const float* __restrict__ w_edge,
                              const float* __restrict__ msg_w1, const float* __restrict__ msg_w2,
                              const float* __restrict__ upd_w,
                              __half* __restrict__ wnt, __half* __restrict__ wet,
                              __half* __restrict__ w1t, __half* __restrict__ w2t,
                              __half* __restrict__ wut)
{
    int z = blockIdx.z;
    const float* src; __half* dst; int K, N;
    if (z == 0)      { src = w_node; dst = wnt; K = 128; N = 128; }
    else if (z == 1) { src = w_edge; dst = wet; K = 128; N = 128; }
    else if (z < 11) {
        int j = z - 2, l = j / 3, p = j % 3;
        src = msg_w1 + (size_t)l * 384 * 256 + (size_t)p * 128 * 256;
        dst = w1t + (size_t)j * 32768; K = 128; N = 256;
    } else if (z < 14) {
        int l = z - 11;
        src = msg_w2 + (size_t)l * 256 * 128; dst = w2t + (size_t)l * 32768; K = 256; N = 128;
    } else {
        int l = z - 14;
        src = upd_w + (size_t)l * 256 * 128; dst = wut + (size_t)l * 32768; K = 256; N = 128;
    }
    int k0 = blockIdx.x * 32, n0 = blockIdx.y * 32;
    if (k0 >= K || n0 >= N) return;
    __shared__ float t[32][33];
    int tx = threadIdx.x & 31, ty = threadIdx.x >> 5;
    for (int i = ty; i < 32; i += 8) {
        int k = k0 + i, n = n0 + tx;
        t[i][tx] = (k < K && n < N) ? src[(size_t)k * N + n] : 0.f;
    }
    __syncthreads();
    for (int i = ty; i < 32; i += 8) {
        int n = n0 + i, k = k0 + tx;
        if (n < N && k < K) dst[(size_t)n * K + k] = __float2half(t[tx][i]);
    }
}

// =====================================================================================
// embed: out = LN(gelu(x@W + b)). K=128, N=128. 64 rows/CTA, 256 thr, 2 CTAs/SM.
// =====================================================================================
__global__ __launch_bounds__(256, 2)
void embed_f16(const float* __restrict__ x, const __half* __restrict__ Wt,
               const float* __restrict__ bias,
               const float* __restrict__ lns, const float* __restrict__ lno,
               float* __restrict__ outf, __half* __restrict__ outh, int M)
{
    extern __shared__ char sm[];
    char* Asm = sm;                 // 64 x 272
    char* Bsm = sm + 17408;         // 128 x 272
    const int tid = threadIdx.x, w = tid >> 5, lane = tid & 31;
    const int wm = w >> 2, wn = w & 3;
    const size_t row0 = (size_t)blockIdx.x * 64;

    for (int i = tid; i < 64 * 16; i += 256) {
        int r = i >> 4, c = i & 15;
        uint32_t o[4] = {0, 0, 0, 0};
        if (row0 + r < (size_t)M) {
            const float* src = x + (row0 + r) * 128 + c * 8;
            float4 a = ((const float4*)src)[0], b = ((const float4*)src)[1];
            __half2 h0 = __floats2half2_rn(a.x, a.y), h1 = __floats2half2_rn(a.z, a.w);
            __half2 h2 = __floats2half2_rn(b.x, b.y), h3 = __floats2half2_rn(b.z, b.w);
            o[0] = *(uint32_t*)&h0; o[1] = *(uint32_t*)&h1; o[2] = *(uint32_t*)&h2; o[3] = *(uint32_t*)&h3;
        }
        *(uint4*)(Asm + r * 272 + c * 16) = *(uint4*)o;
    }
    for (int i = tid; i < 128 * 16; i += 256) {
        int r = i >> 4, c = i & 15;
        *(uint4*)(Bsm + r * 272 + c * 16) = *(const uint4*)(Wt + r * 128 + c * 8);
    }
    __syncthreads();

    float acc[2][4][4] = {};
    mma_loop<128, 4>(s2u(Asm), s2u(Bsm), acc, wm, wn, lane);
    __syncthreads();

    float* Csm = (float*)sm;   // 64 x 132
    const int gid = lane >> 2, tig = lane & 3;
    const int rb = wm * 32 + gid, cb = wn * 32 + tig * 2;
#pragma unroll
    for (int i = 0; i < 2; i++)
#pragma unroll
        for (int nt = 0; nt < 4; nt++) {
            int col = cb + nt * 8;
            int r = rb + i * 16;
            Csm[r * 132 + col]           = gelu_tanh(acc[i][nt][0] + bias[col]);
            Csm[r * 132 + col + 1]       = gelu_tanh(acc[i][nt][1] + bias[col + 1]);
            Csm[(r + 8) * 132 + col]     = gelu_tanh(acc[i][nt][2] + bias[col]);
            Csm[(r + 8) * 132 + col + 1] = gelu_tanh(acc[i][nt][3] + bias[col + 1]);
        }
    __syncthreads();

    int r = tid >> 2, s = tid & 3;
    float4 v[8];
    float sum = 0.f;
#pragma unroll
    for (int k = 0; k < 8; k++) {
        v[k] = *(float4*)&Csm[r * 132 + s * 4 + k * 16];
        sum += v[k].x + v[k].y + v[k].z + v[k].w;
    }
    sum += __shfl_xor_sync(0xffffffffu, sum, 1);
    sum += __shfl_xor_sync(0xffffffffu, sum, 2);
    float mean = sum * (1.0f / 128.0f);
    float q = 0.f;
#pragma unroll
    for (int k = 0; k < 8; k++) {
        float dx = v[k].x - mean, dy = v[k].y - mean, dz = v[k].z - mean, dw = v[k].w - mean;
        q += dx * dx + dy * dy + dz * dz + dw * dw;
    }
    q += __shfl_xor_sync(0xffffffffu, q, 1);
    q += __shfl_xor_sync(0xffffffffu, q, 2);
    float rstd = rsqrtf(q * (1.0f / 128.0f) + 1e-5f);

    size_t row = row0 + r;
    if (row < (size_t)M) {
#pragma unroll
        for (int k = 0; k < 8; k++) {
            int col = s * 4 + k * 16;
            float4 sc = *(const float4*)(lns + col), of = *(const float4*)(lno + col);
            float4 o;
            o.x = (v[k].x - mean) * rstd * sc.x + of.x;
            o.y = (v[k].y - mean) * rstd * sc.y + of.y;
            o.z = (v[k].z - mean) * rstd * sc.z + of.z;
            o.w = (v[k].w - mean) * rstd * sc.w + of.w;
            if (outf) *(float4*)(outf + row * 128 + col) = o;
            if (outh) {
                __half2 h0 = __floats2half2_rn(o.x, o.y), h1 = __floats2half2_rn(o.z, o.w);
                ((uint32_t*)(outh + row * 128 + col))[0] = *(uint32_t*)&h0;
                ((uint32_t*)(outh + row * 128 + col))[1] = *(uint32_t*)&h1;
            }
        }
    }
}

// =====================================================================================
// gemm1: C[M,256] = A[M,128] @ Bt[256][128]. 64 rows/CTA, 256 thr, 2 CTAs/SM.
// =====================================================================================
__global__ __launch_bounds__(256, 2)
void gemm1_f16(const __half* __restrict__ A, const __half* __restrict__ Bt,
               __half* __restrict__ C, int M)
{
    extern __shared__ char sm[];
    char* Asm = sm;                 // 64 x 272
    char* Bsm = sm + 17408;         // 256 x 272
    const int tid = threadIdx.x, w = tid >> 5, lane = tid & 31;
    const int wm = w >> 2, wn = w & 3;
    const size_t row0 = (size_t)blockIdx.x * 64;

    for (int i = tid; i < 64 * 16; i += 256) {
        int r = i >> 4, c = i & 15;
        uint4 v = make_uint4(0, 0, 0, 0);
        if (row0 + r < (size_t)M) v = *(const uint4*)(A + (row0 + r) * 128 + c * 8);
        *(uint4*)(Asm + r * 272 + c * 16) = v;
    }
    for (int i = tid; i < 256 * 16; i += 256) {
        int r = i >> 4, c = i & 15;
        *(uint4*)(Bsm + r * 272 + c * 16) = *(const uint4*)(Bt + (size_t)r * 128 + c * 8);
    }
    __syncthreads();

    float acc[2][8][4] = {};
    mma_loop<128, 8>(s2u(Asm), s2u(Bsm), acc, wm, wn, lane);

    const int gid = lane >> 2, tig = lane & 3;
    const int rb = wm * 32 + gid, cb = wn * 64 + tig * 2;
#pragma unroll
    for (int i = 0; i < 2; i++) {
        size_t r = row0 + rb + i * 16;
#pragma unroll
        for (int nt = 0; nt < 8; nt++) {
            int col = cb + nt * 8;
            __half2 h01 = __floats2half2_rn(acc[i][nt][0], acc[i][nt][1]);
            __half2 h23 = __floats2half2_rn(acc[i][nt][2], acc[i][nt][3]);
            if (r < (size_t)M)     *(__half2*)(C + r * 256 + col) = h01;
            if (r + 8 < (size_t)M) *(__half2*)(C + (r + 8) * 256 + col) = h23;
        }
    }
}

// =====================================================================================
// edge_dual: persistent, TWO independent 256-thread groups per CTA, 32-edge tiles,
// 2-deep cp.async pipeline per group, shared read-only B1/B2.
// smem: idx 1024 | b1s 1024 | b2s 512 | B1 65536 | B2 65536
//       | per group: AE 2x8192, PS 16384, PR 16384 (=49152) x2  -> total 231936
// =====================================================================================
__global__ __launch_bounds__(512, 1)
void edge_dual_f16(const __half* __restrict__ eh,
                   const __half* __restrict__ Ps, const __half* __restrict__ Pr,
                   const __half* __restrict__ W1ct, const float* __restrict__ b1,
                   const __half* __restrict__ W2t,  const float* __restrict__ b2,
                   const int* __restrict__ snd, const int* __restrict__ rcv,
                   float* __restrict__ agg, int E)
{
    extern __shared__ char sm[];
    int*   idxb = (int*)sm;              // [2 grp][2 slot][64] (32 snd | 32 rcv)
    float* b1s  = (float*)(sm + 1024);   // 256
    float* b2s  = (float*)(sm + 2048);   // 128
    char* B1 = sm + 2560;                // 65536
    char* B2 = sm + 68096;               // 65536
    char* GRP = sm + 133632;             // 2 x 49152
    const int tid = threadIdx.x;

    // joint weight staging (all 512 threads), then groups diverge permanently
    for (int i = tid; i < 256 * 16; i += 512) {
        int r = i >> 4, c = i & 15;
        *(uint4*)(B1 + r * 256 + (((uint32_t)c * 16) ^ ((r & 7) << 4))) =
            *(const uint4*)(W1ct + (size_t)r * 128 + c * 8);
    }
    for (int i = tid; i < 128 * 32; i += 512) {
        int r = i >> 5, c = i & 31;
        *(uint4*)(B2 + r * 512 + (((uint32_t)c * 16) ^ ((r & 7) << 4))) =
            *(const uint4*)(W2t + (size_t)r * 256 + c * 8);
    }
    if (tid < 256) b1s[tid] = b1[tid];
    if (tid >= 256 && tid < 384) b2s[tid - 256] = b2[tid - 256];
    __syncthreads();

    const int g = tid >> 8, t = tid & 255;
    const int w2 = t >> 5, lane = t & 31;
    const int wm = w2 >> 2, wn = w2 & 3;          // wm 0..1 (16-row tiles), wn 0..3
    const int gid = lane >> 2, tig = lane & 3;
    const int barid = 1 + g;

    char* AE  = GRP + g * 49152;                  // 2 x 8192
    char* PSb = AE + 16384;                       // 16384 (becomes m1)
    char* PRb = PSb + 16384;                      // 16384
    int*  gidx = idxb + g * 128;                  // [slot][64]
    const uint32_t gidx_u = s2u(gidx), ae_u = s2u(AE);
    const uint32_t ps_u = s2u(PSb), pr_u = s2u(PRb);
    const uint32_t b1_u = s2u(B1), b2_u = s2u(B2);

    const int nblk = (E + 31) >> 5;
    const int t0 = blockIdx.x * 2 + g, stride = gridDim.x * 2;
    const int T = (nblk > t0) ? ((nblk - t0 + stride - 1) / stride) : 0;
    if (T <= 0) return;

    const int idx_clamp = ((E - 4) > 0) ? ((E - 4) & ~3) : 0;

    auto issue_idxA = [&](int u) {
        int e0n = (t0 + u * stride) << 5;
        int slot = u & 1;
        if (t < 8) {
            int off = e0n + t * 4; if (off > idx_clamp) off = idx_clamp;
            cpa16(gidx_u + slot * 256 + t * 16, snd + off);
        } else if (t < 16) {
            int t2 = t - 8;
            int off = e0n + t2 * 4; if (off > idx_clamp) off = idx_clamp;
            cpa16(gidx_u + slot * 256 + 128 + t2 * 16, rcv + off);
        }
        for (int i = t; i < 512; i += 256) {       // 32 rows x 16 chunks
            int r = i >> 4, c = i & 15;
            int eg = e0n + r; if (eg > E - 1) eg = E - 1;
            cpa16(ae_u + slot * 8192 + r * 256 + (((uint32_t)c * 16) ^ ((r & 7) << 4)),
                  eh + (size_t)eg * 128 + c * 8);
        }
    };

    issue_idxA(0);
    CP_COMMIT();

    for (int u = 0; u < T; u++) {
        const int slot = u & 1;
        const int e0 = (t0 + u * stride) << 5;

        CP_WAIT(0);          // idx(u), A_e(u) ready
        barg(barid);

        // snapshot receiver ids (tail-masked) for scatter
        const int r0 = wm * 16 + gid, r1 = r0 + 8;
        const int rv0 = (e0 + r0 < E) ? gidx[slot * 64 + 32 + r0] : -1;
        const int rv1 = (e0 + r1 < E) ? gidx[slot * 64 + 32 + r1] : -1;

        // issue PS/PR(u) gathers (G1): 32 rows x 32 chunks each
        for (int i = t; i < 1024; i += 256) {
            int r = i >> 5, c = i & 31;
            int sv = gidx[slot * 64 + r];
            cpa16(ps_u + r * 512 + (((uint32_t)c * 16) ^ ((r & 7) << 4)),
                  Ps + (size_t)sv * 256 + c * 8);
        }
        for (int i = t; i < 1024; i += 256) {
            int r = i >> 5, c = i & 31;
            int rv = gidx[slot * 64 + 32 + r];
            cpa16(pr_u + r * 512 + (((uint32_t)c * 16) ^ ((r & 7) << 4)),
                  Pr + (size_t)rv * 256 + c * 8);
        }
        CP_COMMIT();

        // issue idx/A_e(u+1) (G2)
        if (u + 1 < T) issue_idxA(u + 1);
        CP_COMMIT();

        // mma1: Pe = A_e @ W1c^T (32x256, K=128) — overlaps PS/PR gather
        float acc1[8][4] = {};
        mma_loop_16sw<128, 8, 256, 256>(ae_u + slot * 8192, b1_u, acc1, wm, wn, lane);

        CP_WAIT(1);          // PS/PR(u) done (G2 still streaming)
        barg(barid);

        // combine: m1 = relu(Pe + PS + PR + b1), in place over PS
#pragma unroll
        for (int nt = 0; nt < 8; nt++) {
            int c = wn * 64 + nt * 8 + tig * 2;
            float bxv = b1s[c], byv = b1s[c + 1];
#pragma unroll
            for (int hh = 0; hh < 2; hh++) {
                int r = wm * 16 + gid + hh * 8;
                uint32_t off = r * 512 + (((uint32_t)(c * 2)) ^ ((r & 7) << 4));
                float2 fa = __half22float2(*(__half2*)(PSb + off));
                float2 fb = __half22float2(*(__half2*)(PRb + off));
                float xx = fmaxf(acc1[nt][2 * hh]     + fa.x + fb.x + bxv, 0.f);
                float yy = fmaxf(acc1[nt][2 * hh + 1] + fa.y + fb.y + byv, 0.f);
                *(__half2*)(PSb + off) = __floats2half2_rn(xx, yy);
            }
        }
        barg(barid);

        // mma2: out = m1 @ W2^T (32x128, K=256)
        float acc2[4][4] = {};
        mma_loop_16sw<256, 4, 512, 512>(ps_u, b2_u, acc2, wm, wn, lane);

        // fragment-direct scatter: float2 RED with bias+relu
#pragma unroll
        for (int nt = 0; nt < 4; nt++) {
            int c = wn * 32 + nt * 8 + tig * 2;
            float2 bb = *(float2*)&b2s[c];
            if (rv0 >= 0) {
                float2 v0 = make_float2(fmaxf(acc2[nt][0] + bb.x, 0.f),
                                        fmaxf(acc2[nt][1] + bb.y, 0.f));
                atomicAdd((float2*)(agg + (size_t)rv0 * 128 + c), v0);
            }
            if (rv1 >= 0) {
                float2 v1 = make_float2(fmaxf(acc2[nt][2] + bb.x, 0.f),
                                        fmaxf(acc2[nt][3] + bb.y, 0.f));
                atomicAdd((float2*)(agg + (size_t)rv1 * 128 + c), v1);
            }
        }
        // next iteration's CP_WAIT(0)+barg orders reuse of PS/PR/idx buffers
    }
}

// =====================================================================================
// node_update: upd = LN(concat(nh, agg) @ Wu + b); out = n + upd.
// K=256, N=128. 64 rows/CTA, 256 thr, 2 CTAs/SM.
// =====================================================================================
__global__ __launch_bounds__(256, 2)
void node_update_f16(const float* __restrict__ nf, const __half* __restrict__ nh,
                     const float* __restrict__ agg, const __half* __restrict__ Wut,
                     const float* __restrict__ bias,
                     const float* __restrict__ lns, const float* __restrict__ lno,
                     float* __restrict__ outf, __half* __restrict__ outh, int M)
{
    extern __shared__ char sm[];
    char* Asm = sm;                 // 64 x 528
    char* Bsm = sm + 33792;         // 128 x 528
    const int tid = threadIdx.x, w = tid >> 5, lane = tid & 31;
    const int wm = w >> 2, wn = w & 3;
    const size_t row0 = (size_t)blockIdx.x * 64;

    for (int i = tid; i < 64 * 32; i += 256) {
        int r = i >> 5, c = i & 31, k0 = c * 8;
        uint32_t o[4] = {0, 0, 0, 0};
        size_t row = row0 + r;
        if (row < (size_t)M) {
            if (k0 < 128) {
                *(uint4*)o = *(const uint4*)(nh + row * 128 + k0);
            } else {
                const float* src = agg + row * 128 + (k0 - 128);
                float4 a = ((const float4*)src)[0], b = ((const float4*)src)[1];
                __half2 h0 = __floats2half2_rn(a.x, a.y), h1 = __floats2half2_rn(a.z, a.w);
                __half2 h2 = __floats2half2_rn(b.x, b.y), h3 = __floats2half2_rn(b.z, b.w);
                o[0] = *(uint32_t*)&h0; o[1] = *(uint32_t*)&h1; o[2] = *(uint32_t*)&h2; o[3] = *(uint32_t*)&h3;
            }
        }
        *(uint4*)(Asm + r * 528 + c * 16) = *(uint4*)o;
    }
    for (int i = tid; i < 128 * 32; i += 256) {
        int r = i >> 5, c = i & 31;
        *(uint4*)(Bsm + r * 528 + c * 16) = *(const uint4*)(Wut + (size_t)r * 256 + c * 8);
    }
    __syncthreads();

    float acc[2][4][4] = {};
    mma_loop<256, 4>(s2u(Asm), s2u(Bsm), acc, wm, wn, lane);
    __syncthreads();

    float* Csm = (float*)Asm;   // 64 x 132
    const int gid = lane >> 2, tig = lane & 3;
    const int rb = wm * 32 + gid, cb = wn * 32 + tig * 2;
#pragma unroll
    for (int i = 0; i < 2; i++)
#pragma unroll
        for (int nt = 0; nt < 4; nt++) {
            int col = cb + nt * 8;
            int r = rb + i * 16;
            Csm[r * 132 + col]           = acc[i][nt][0] + bias[col];
            Csm[r * 132 + col + 1]       = acc[i][nt][1] + bias[col + 1];
            Csm[(r + 8) * 132 + col]     = acc[i][nt][2] + bias[col];
            Csm[(r + 8) * 132 + col + 1] = acc[i][nt][3] + bias[col + 1];
        }
    __syncthreads();

    int r = tid >> 2, s = tid & 3;
    float4 v[8];
    float sum = 0.f;
#pragma unroll
    for (int k = 0; k < 8; k++) {
        v[k] = *(float4*)&Csm[r * 132 + s * 4 + k * 16];
        sum += v[k].x + v[k].y + v[k].z + v[k].w;
    }
    sum += __shfl_xor_sync(0xffffffffu, sum, 1);
    sum += __shfl_xor_sync(0xffffffffu, sum, 2);
    float mean = sum * (1.0f / 128.0f);
    float q = 0.f;
#pragma unroll
    for (int k = 0; k < 8; k++) {
        float dx = v[k].x - mean, dy = v[k].y - mean, dz = v[k].z - mean, dw = v[k].w - mean;
        q += dx * dx + dy * dy + dz * dz + dw * dw;
    }
    q += __shfl_xor_sync(0xffffffffu, q, 1);
    q += __shfl_xor_sync(0xffffffffu, q, 2);
    float rstd = rsqrtf(q * (1.0f / 128.0f) + 1e-5f);

    size_t row = row0 + r;
    if (row < (size_t)M) {
#pragma unroll
        for (int k = 0; k < 8; k++) {
            int col = s * 4 + k * 16;
            float4 sc = *(const float4*)(lns + col), of = *(const float4*)(lno + col);
            float4 res = *(const float4*)(nf + row * 128 + col);
            float4 o;
            o.x = res.x + (v[k].x - mean) * rstd * sc.x + of.x;
            o.y = res.y + (v[k].y - mean) * rstd * sc.y + of.y;
            o.z = res.z + (v[k].z - mean) * rstd * sc.z + of.z;
            o.w = res.w + (v[k].w - mean) * rstd * sc.w + of.w;
            if (outf) *(float4*)(outf + row * 128 + col) = o;
            if (outh) {
                __half2 h0 = __floats2half2_rn(o.x, o.y), h1 = __floats2half2_rn(o.z, o.w);
                ((uint32_t*)(outh + row * 128 + col))[0] = *(uint32_t*)&h0;
                ((uint32_t*)(outh + row * 128 + col))[1] = *(uint32_t*)&h1;
            }
        }
    }
}

// =====================================================================================
extern "C" void kernel_launch(void* const* d_in, const int* in_sizes, int n_in,
                              void* d_out, int out_size)
{
    const float* nodes     = (const float*)d_in[0];
    const float* edges     = (const float*)d_in[1];
    const int*   senders   = (const int*)d_in[2];
    const int*   receivers = (const int*)d_in[3];
    const float* w_node    = (const float*)d_in[4];
    const float* b_node    = (const float*)d_in[5];
    const float* w_edge    = (const float*)d_in[6];
    const float* b_edge    = (const float*)d_in[7];
    const float* ln_n_s    = (const float*)d_in[8];
    const float* ln_n_o    = (const float*)d_in[9];
    const float* ln_e_s    = (const float*)d_in[10];
    const float* ln_e_o    = (const float*)d_in[11];
    const float* msg_w1    = (const float*)d_in[12];
    const float* msg_b1    = (const float*)d_in[13];
    const float* msg_w2    = (const float*)d_in[14];
    const float* msg_b2    = (const float*)d_in[15];
    const float* upd_w     = (const float*)d_in[16];
    const float* upd_b     = (const float*)d_in[17];
    const float* ln_s      = (const float*)d_in[18];
    const float* ln_o      = (const float*)d_in[19];

    const int N = in_sizes[0] / D;
    const int E = in_sizes[1] / D;

    int dev = 0, nsm = 148;
    cudaGetDevice(&dev);
    cudaDeviceGetAttribute(&nsm, cudaDevAttrMultiProcessorCount, dev);

    float *pn, *pagg;
    __half *pnh, *peh, *pPs, *pPr, *pwnt, *pwet, *pw1t, *pw2t, *pwut;
    cudaGetSymbolAddress((void**)&pn,   g_n);
    cudaGetSymbolAddress((void**)&pagg, g_agg);
    cudaGetSymbolAddress((void**)&pnh,  g_nh);
    cudaGetSymbolAddress((void**)&peh,  g_eh);
    cudaGetSymbolAddress((void**)&pPs,  g_Psh);
    cudaGetSymbolAddress((void**)&pPr,  g_Prh);
    cudaGetSymbolAddress((void**)&pwnt, g_wnt);
    cudaGetSymbolAddress((void**)&pwet, g_wet);
    cudaGetSymbolAddress((void**)&pw1t, g_w1t);
    cudaGetSymbolAddress((void**)&pw2t, g_w2t);
    cudaGetSymbolAddress((void**)&pwut, g_wut);

    const size_t embed_smem = 52224;
    const size_t g1_smem    = 87040;
    const size_t edge_smem  = 231936;
    const size_t upd_smem   = 101376;

    cudaFuncSetAttribute(embed_f16,       cudaFuncAttributeMaxDynamicSharedMemorySize, (int)embed_smem);
    cudaFuncSetAttribute(gemm1_f16,       cudaFuncAttributeMaxDynamicSharedMemorySize, (int)g1_smem);
    cudaFuncSetAttribute(edge_dual_f16,   cudaFuncAttributeMaxDynamicSharedMemorySize, (int)edge_smem);
    cudaFuncSetAttribute(node_update_f16, cudaFuncAttributeMaxDynamicSharedMemorySize, (int)upd_smem);

    // ---- all weight transposes in one launch ----
    transpose_all<<<dim3(8, 8, 17), 256>>>(w_node, w_edge, msg_w1, msg_w2, upd_w,
                                           pwnt, pwet, pw1t, pw2t, pwut);

    // ---- embeddings ----
    embed_f16<<<(N + 63) / 64, 256, embed_smem>>>(nodes, pwnt, b_node, ln_n_s, ln_n_o, pn, pnh, N);
    embed_f16<<<(E + 63) / 64, 256, embed_smem>>>(edges, pwet, b_edge, ln_e_s, ln_e_o, (float*)nullptr, peh, E);

    // ---- layers ----
    for (int l = 0; l < 3; l++) {
        gemm1_f16<<<(N + 63) / 64, 256, g1_smem>>>(pnh, pw1t + (size_t)(l * 3 + 0) * 32768, pPs, N);
        gemm1_f16<<<(N + 63) / 64, 256, g1_smem>>>(pnh, pw1t + (size_t)(l * 3 + 1) * 32768, pPr, N);
        cudaMemsetAsync(pagg, 0, (size_t)N * D * sizeof(float), 0);
        edge_dual_f16<<<nsm, 512, edge_smem>>>(
            peh, pPs, pPr,
            pw1t + (size_t)(l * 3 + 2) * 32768, msg_b1 + (size_t)l * 256,
            pw2t + (size_t)l * 32768, msg_b2 + (size_t)l * 128,
            senders, receivers, pagg, E);
        float* nout = (l == 2) ? (float*)d_out : pn;
        __half* nhout = (l == 2) ? (__half*)nullptr : pnh;
        node_update_f16<<<(N + 63) / 64, 256, upd_smem>>>(
            pn, pnh, pagg, pwut + (size_t)l * 32768, upd_b + (size_t)l * 128,
            ln_s + (size_t)l * 128, ln_o + (size_t)l * 128, nout, nhout, N);
    }
}